// round 3
// baseline (speedup 1.0000x reference)
#include <cuda_runtime.h>
#include <math.h>

#define EE 512
#define HH 8
#define BB 4
#define SS 2048
#define NROW (BB*SS)            // 8192
#define FF 2048                 // 2LH + 2AH
#define LH 512
#define OFF_U 0
#define OFF_V 512
#define OFF_Q 1024
#define OFF_K 1536

// Scratch (allocation-free rule: __device__ globals)
__device__ float g_normed[(size_t)NROW*EE];   // 16.8 MB
__device__ float g_proj[(size_t)NROW*FF];     // 67 MB
__device__ float g_attn[(size_t)NROW*LH];     // 16.8 MB

// ---------------- helpers ----------------
__device__ __forceinline__ void cpa16(void* dst, const void* src) {
    unsigned u = (unsigned)__cvta_generic_to_shared(dst);
    asm volatile("cp.async.cg.shared.global [%0], [%1], 16;\n" :: "r"(u), "l"(src));
}
__device__ __forceinline__ void cp_commit() { asm volatile("cp.async.commit_group;\n"); }
__device__ __forceinline__ void cp_wait0() { asm volatile("cp.async.wait_group 0;\n"); }
__device__ __forceinline__ void cp_wait1() { asm volatile("cp.async.wait_group 1;\n"); }

__device__ __forceinline__ void mma_tf32(float* d, const unsigned* a, const unsigned* b) {
    asm volatile(
        "mma.sync.aligned.m16n8k8.row.col.f32.tf32.tf32.f32 "
        "{%0,%1,%2,%3}, {%4,%5,%6,%7}, {%8,%9}, {%0,%1,%2,%3};\n"
        : "+f"(d[0]), "+f"(d[1]), "+f"(d[2]), "+f"(d[3])
        : "r"(a[0]), "r"(a[1]), "r"(a[2]), "r"(a[3]), "r"(b[0]), "r"(b[1]));
}

__device__ __forceinline__ float2 block_reduce_sum2(float sum, float sq) {
    __shared__ float sh[16];
    int lane = threadIdx.x & 31, w = threadIdx.x >> 5;
#pragma unroll
    for (int o = 16; o > 0; o >>= 1) {
        sum += __shfl_xor_sync(0xffffffffu, sum, o);
        sq  += __shfl_xor_sync(0xffffffffu, sq, o);
    }
    if (lane == 0) { sh[w] = sum; sh[8 + w] = sq; }
    __syncthreads();
    float s = 0.f, q = 0.f;
#pragma unroll
    for (int i = 0; i < 8; i++) { s += sh[i]; q += sh[8 + i]; }
    return make_float2(s, q);
}

// ---------------- 1) input LayerNorm ----------------
__global__ __launch_bounds__(256) void ln_in_kernel(const float* __restrict__ x,
                                                    const float* __restrict__ g,
                                                    const float* __restrict__ be) {
    const int row = blockIdx.x, t = threadIdx.x;
    const float* xr = x + (size_t)row * EE;
    float v0 = xr[t], v1 = xr[t + 256];
    float2 r = block_reduce_sum2(v0 + v1, v0 * v0 + v1 * v1);
    float mu = r.x * (1.f / 512.f);
    float var = r.y * (1.f / 512.f) - mu * mu;
    float rs = rsqrtf(var + 1e-6f);
    float* orow = g_normed + (size_t)row * EE;
    orow[t]       = (v0 - mu) * rs * g[t]       + be[t];
    orow[t + 256] = (v1 - mu) * rs * g[t + 256] + be[t + 256];
}

// ---------------- 2) projection GEMM (tf32, cp.async double-buffered) ----------------
// 128x128 block tile, BK=32, 256 threads, 8 warps (2m x 4n), warp tile 64x32
#define PROJ_SMEM ((2*128*36 + 2*32*132) * 4)
__global__ __launch_bounds__(256) void gemm_proj_kernel(const float* __restrict__ W) {
    extern __shared__ float sm[];
    float (*As)[128][36] = reinterpret_cast<float(*)[128][36]>(sm);              // [st][m][k]
    float (*Bs)[32][132] = reinterpret_cast<float(*)[32][132]>(sm + 2*128*36);   // [st][k][n]
    const int t = threadIdx.x;
    const int wid = t >> 5, lane = t & 31;
    const int gid = lane >> 2, tig = lane & 3;
    const int warp_m = wid & 1, warp_n = wid >> 1;
    const int m0 = warp_m * 64, n0 = warp_n * 32;
    const int bm = blockIdx.y * 128, bn = blockIdx.x * 128;

    const int a_kq = t & 7, a_m = t >> 3;
    const int b_n4 = t & 31, b_k = t >> 5;

    float acc[4][4][4] = {};

#define LOAD_PROJ_ST(st, k0) do {                                                      \
        _Pragma("unroll")                                                              \
        for (int i = 0; i < 4; i++) {                                                  \
            const int m = a_m + i * 32;                                                \
            cpa16(&As[st][m][a_kq*4], &g_normed[(size_t)(bm + m) * EE + (k0) + a_kq*4]); \
        }                                                                              \
        _Pragma("unroll")                                                              \
        for (int i = 0; i < 4; i++) {                                                  \
            const int kk = b_k + i * 8;                                                \
            cpa16(&Bs[st][kk][b_n4*4], &W[(size_t)((k0) + kk) * FF + bn + b_n4*4]);    \
        }                                                                              \
    } while (0)

    LOAD_PROJ_ST(0, 0); cp_commit();

    for (int it = 0; it < 16; ++it) {
        if (it < 15) { LOAD_PROJ_ST((it + 1) & 1, (it + 1) * 32); cp_commit(); cp_wait1(); }
        else cp_wait0();
        __syncthreads();
        const int st = it & 1;
#pragma unroll
        for (int ks = 0; ks < 32; ks += 8) {
            unsigned af[4][4], bf[4][2];
#pragma unroll
            for (int mi = 0; mi < 4; mi++) {
                const int mr = m0 + mi * 16;
                af[mi][0] = __float_as_uint(As[st][mr + gid][ks + tig]);
                af[mi][1] = __float_as_uint(As[st][mr + gid + 8][ks + tig]);
                af[mi][2] = __float_as_uint(As[st][mr + gid][ks + tig + 4]);
                af[mi][3] = __float_as_uint(As[st][mr + gid + 8][ks + tig + 4]);
            }
#pragma unroll
            for (int ni = 0; ni < 4; ni++) {
                const int nc = n0 + ni * 8 + gid;
                bf[ni][0] = __float_as_uint(Bs[st][ks + tig][nc]);
                bf[ni][1] = __float_as_uint(Bs[st][ks + tig + 4][nc]);
            }
#pragma unroll
            for (int mi = 0; mi < 4; mi++)
#pragma unroll
                for (int ni = 0; ni < 4; ni++)
                    mma_tf32(acc[mi][ni], af[mi], bf[ni]);
        }
        __syncthreads();
    }
#pragma unroll
    for (int mi = 0; mi < 4; mi++)
#pragma unroll
        for (int ni = 0; ni < 4; ni++) {
            const int r = bm + m0 + mi * 16 + gid;
            const int c = bn + n0 + ni * 8 + 2 * tig;
            *(float2*)&g_proj[(size_t)r * FF + c]       = make_float2(acc[mi][ni][0], acc[mi][ni][1]);
            *(float2*)&g_proj[(size_t)(r + 8) * FF + c] = make_float2(acc[mi][ni][2], acc[mi][ni][3]);
        }
}

// ---------------- 3) causal silu-attention (tf32, 128-row Q tiles, cp.async KV pipeline) ----------------
// grid (16 q-tiles, 32 b*h), 512 threads = 16 warps (4n x 4m)
#define ATTN_SMEM ((128*68 + 128*68 + 2*64*68 + 2*64*68) * 4)
__global__ __launch_bounds__(512) void attn_kernel() {
    extern __shared__ float sm[];
    float (*qs)[68] = reinterpret_cast<float(*)[68]>(sm);                     // [128][d]
    float (*ps)[68] = reinterpret_cast<float(*)[68]>(sm + 128 * 68);          // [128][m]
    float (*ks)[64][68] = reinterpret_cast<float(*)[64][68]>(sm + 2 * 128 * 68);            // [st][64][d]
    float (*vs)[64][68] = reinterpret_cast<float(*)[64][68]>(sm + 2 * 128 * 68 + 2*64*68);  // [st][64][d]

    const int t = threadIdx.x;
    const int wid = t >> 5, lane = t & 31;
    const int gid = lane >> 2, tig = lane & 3;
    const int warp_n = wid >> 2;       // 0..3 : 32 query rows each
    const int warp_m = wid & 3;        // 0..3 : 16 key cols each
    const int n0 = warp_n * 32, m0w = warp_m * 16;

    const int nt = 15 - blockIdx.x;    // largest workloads first
    const int bh = blockIdx.y;
    const int b = bh >> 3, h = bh & 7;
    const int nbase = nt << 7;
    const size_t base = (size_t)b * SS;
    const int hd = h << 6;

    const int d4 = t & 15, ldr = t >> 4;   // 16 float4 per row, 32 rows per pass

    // Q tile: 128 rows
#pragma unroll
    for (int i = 0; i < 4; i++) {
        const int row = ldr + i * 32;
        cpa16(&qs[row][d4 * 4], &g_proj[(base + nbase + row) * FF + OFF_Q + hd + d4 * 4]);
    }

#define LOAD_KV_ST(st, m0b) do {                                                        \
        _Pragma("unroll")                                                               \
        for (int i = 0; i < 2; i++) {                                                   \
            const int row = ldr + i * 32;                                               \
            const float* rowp = &g_proj[(base + (m0b) + row) * FF + hd + d4 * 4];       \
            cpa16(&ks[st][row][d4 * 4], rowp + OFF_K);                                  \
            cpa16(&vs[st][row][d4 * 4], rowp + OFF_V);                                  \
        }                                                                               \
    } while (0)

    LOAD_KV_ST(0, 0); cp_commit();

    float o[2][2][4] = {};
    const int nkt = 2 * nt + 2;

    for (int kt = 0; kt < nkt; ++kt) {
        const int m0b = kt << 6;
        if (kt + 1 < nkt) { LOAD_KV_ST((kt + 1) & 1, (kt + 1) << 6); cp_commit(); cp_wait1(); }
        else cp_wait0();
        __syncthreads();
        const int st = kt & 1;

        // S = Q @ K^T  (warp: 32n x 16m)
        float s[2][2][4] = {};
#pragma unroll
        for (int ks8 = 0; ks8 < 8; ks8++) {
            const int d0 = ks8 * 8;
            unsigned aq[2][4], bk[2][2];
#pragma unroll
            for (int ni = 0; ni < 2; ni++) {
                const int r = n0 + ni * 16;
                aq[ni][0] = __float_as_uint(qs[r + gid][d0 + tig]);
                aq[ni][1] = __float_as_uint(qs[r + gid + 8][d0 + tig]);
                aq[ni][2] = __float_as_uint(qs[r + gid][d0 + tig + 4]);
                aq[ni][3] = __float_as_uint(qs[r + gid + 8][d0 + tig + 4]);
            }
#pragma unroll
            for (int mi = 0; mi < 2; mi++) {
                const int c = m0w + mi * 8 + gid;
                bk[mi][0] = __float_as_uint(ks[st][c][d0 + tig]);
                bk[mi][1] = __float_as_uint(ks[st][c][d0 + tig + 4]);
            }
#pragma unroll
            for (int ni = 0; ni < 2; ni++)
#pragma unroll
                for (int mi = 0; mi < 2; mi++)
                    mma_tf32(s[ni][mi], aq[ni], bk[mi]);
        }

        // silu * causal mask -> ps
#pragma unroll
        for (int ni = 0; ni < 2; ni++)
#pragma unroll
            for (int mi = 0; mi < 2; mi++) {
                const int nl = n0 + ni * 16 + gid;
                const int ml = m0w + mi * 8 + 2 * tig;
#pragma unroll
                for (int cc = 0; cc < 4; cc++) {
                    const int rr = nl + (cc >> 1) * 8;
                    const int mm = ml + (cc & 1);
                    float x = s[ni][mi][cc];
                    float p = x / (1.0f + __expf(-x));
                    if (m0b + mm > nbase + rr) p = 0.0f;
                    ps[rr][mm] = p;
                }
            }
        __syncthreads();

        // O += P @ V  (warp: 32n x 16d)
#pragma unroll
        for (int kk8 = 0; kk8 < 8; kk8++) {
            const int mk = kk8 * 8;
            unsigned ap[2][4], bv[2][2];
#pragma unroll
            for (int ni = 0; ni < 2; ni++) {
                const int r = n0 + ni * 16;
                ap[ni][0] = __float_as_uint(ps[r + gid][mk + tig]);
                ap[ni][1] = __float_as_uint(ps[r + gid + 8][mk + tig]);
                ap[ni][2] = __float_as_uint(ps[r + gid][mk + tig + 4]);
                ap[ni][3] = __float_as_uint(ps[r + gid + 8][mk + tig + 4]);
            }
#pragma unroll
            for (int di = 0; di < 2; di++) {
                const int c = m0w + di * 8 + gid;
                bv[di][0] = __float_as_uint(vs[st][mk + tig][c]);
                bv[di][1] = __float_as_uint(vs[st][mk + tig + 4][c]);
            }
#pragma unroll
            for (int ni = 0; ni < 2; ni++)
#pragma unroll
                for (int di = 0; di < 2; di++)
                    mma_tf32(o[ni][di], ap[ni], bv[di]);
        }
        __syncthreads();   // protect vs[(kt+1)&1] against next iteration's prefetch
    }

#pragma unroll
    for (int ni = 0; ni < 2; ni++)
#pragma unroll
        for (int di = 0; di < 2; di++) {
            const size_t r = base + nbase + n0 + ni * 16 + gid;
            const int c = hd + m0w + di * 8 + 2 * tig;
            *(float2*)&g_attn[r * LH + c]       = make_float2(o[ni][di][0], o[ni][di][1]);
            *(float2*)&g_attn[(r + 8) * LH + c] = make_float2(o[ni][di][2], o[ni][di][3]);
        }
}

// ---------------- 4) output LN * u + residual ----------------
__global__ __launch_bounds__(256) void out_kernel(const float* __restrict__ ue,
                                                  const float* __restrict__ g,
                                                  const float* __restrict__ be,
                                                  float* __restrict__ out) {
    const int row = blockIdx.x, t = threadIdx.x;
    const float* ar = g_attn + (size_t)row * LH;
    float a0 = ar[t], a1 = ar[t + 256];
    float2 r = block_reduce_sum2(a0 + a1, a0 * a0 + a1 * a1);
    float mu = r.x * (1.f / 512.f);
    float var = r.y * (1.f / 512.f) - mu * mu;
    float rs = rsqrtf(var + 1e-6f);
    const float* ur  = g_proj + (size_t)row * FF + OFF_U;
    const float* uer = ue + (size_t)row * EE;
    float* orow = out + (size_t)row * EE;
    orow[t]       = uer[t]       + ((a0 - mu) * rs * g[t]       + be[t])       * ur[t];
    orow[t + 256] = uer[t + 256] + ((a1 - mu) * rs * g[t + 256] + be[t + 256]) * ur[t + 256];
}

extern "C" void kernel_launch(void* const* d_in, const int* in_sizes, int n_in,
                              void* d_out, int out_size) {
    (void)in_sizes; (void)n_in; (void)out_size;
    const float* ue   = (const float*)d_in[0];
    const float* uvqk = (const float*)d_in[2];
    const float* ing  = (const float*)d_in[3];
    const float* inb  = (const float*)d_in[4];
    const float* outg = (const float*)d_in[5];
    const float* outb = (const float*)d_in[6];
    float* out = (float*)d_out;

    cudaFuncSetAttribute(gemm_proj_kernel, cudaFuncAttributeMaxDynamicSharedMemorySize, PROJ_SMEM);
    cudaFuncSetAttribute(attn_kernel, cudaFuncAttributeMaxDynamicSharedMemorySize, ATTN_SMEM);

    ln_in_kernel<<<NROW, 256>>>(ue, ing, inb);
    gemm_proj_kernel<<<dim3(FF / 128, NROW / 128), 256, PROJ_SMEM>>>(uvqk);
    attn_kernel<<<dim3(SS / 128, BB * HH), 512, ATTN_SMEM>>>();
    out_kernel<<<NROW, 256>>>(ue, outg, outb, out);
}

// round 5
// speedup vs baseline: 1.6986x; 1.6986x over previous
#include <cuda_runtime.h>
#include <cuda_fp16.h>
#include <math.h>
#include <stdint.h>

#define EE 512
#define HH 8
#define BB 4
#define SS 2048
#define NROW (BB*SS)            // 8192
#define FF 2048                 // 2LH + 2AH
#define LH 512

// qkv packed layout per row: V @0, Q @512, K @1024 (halves)
#define QKV_W 1536
#define QO_V 0
#define QO_Q 512
#define QO_K 1024

// Scratch (allocation-free rule: __device__ globals)
__device__ __half g_normed[(size_t)NROW*EE];   // 8.4 MB
__device__ __half g_Wt[(size_t)FF*EE];         // 2 MB (W transposed, fp16)
__device__ __half g_qkv[(size_t)NROW*QKV_W];   // 25 MB (V,Q,K fp16)
__device__ float  g_u[(size_t)NROW*LH];        // 16.8 MB (U fp32)
__device__ float  g_attn[(size_t)NROW*LH];     // 16.8 MB

// ---------------- helpers ----------------
__device__ __forceinline__ void cpa16(void* dst, const void* src) {
    unsigned u = (unsigned)__cvta_generic_to_shared(dst);
    asm volatile("cp.async.cg.shared.global [%0], [%1], 16;\n" :: "r"(u), "l"(src));
}
__device__ __forceinline__ void cp_commit() { asm volatile("cp.async.commit_group;\n"); }
__device__ __forceinline__ void cp_wait0() { asm volatile("cp.async.wait_group 0;\n"); }
__device__ __forceinline__ void cp_wait1() { asm volatile("cp.async.wait_group 1;\n"); }

__device__ __forceinline__ uint32_t smem_u32(const void* p) {
    return (uint32_t)__cvta_generic_to_shared(p);
}
__device__ __forceinline__ void ldsm_x4(uint32_t* r, uint32_t addr) {
    asm volatile("ldmatrix.sync.aligned.m8n8.x4.shared.b16 {%0,%1,%2,%3}, [%4];"
                 : "=r"(r[0]), "=r"(r[1]), "=r"(r[2]), "=r"(r[3]) : "r"(addr));
}
__device__ __forceinline__ void ldsm_x4_t(uint32_t* r, uint32_t addr) {
    asm volatile("ldmatrix.sync.aligned.m8n8.x4.trans.shared.b16 {%0,%1,%2,%3}, [%4];"
                 : "=r"(r[0]), "=r"(r[1]), "=r"(r[2]), "=r"(r[3]) : "r"(addr));
}
__device__ __forceinline__ void mma_f16(float* d, const uint32_t* a, const uint32_t* b) {
    asm volatile(
        "mma.sync.aligned.m16n8k16.row.col.f32.f16.f16.f32 "
        "{%0,%1,%2,%3}, {%4,%5,%6,%7}, {%8,%9}, {%0,%1,%2,%3};\n"
        : "+f"(d[0]), "+f"(d[1]), "+f"(d[2]), "+f"(d[3])
        : "r"(a[0]), "r"(a[1]), "r"(a[2]), "r"(a[3]), "r"(b[0]), "r"(b[1]));
}

__device__ __forceinline__ float2 block_reduce_sum2(float sum, float sq) {
    __shared__ float sh[16];
    int lane = threadIdx.x & 31, w = threadIdx.x >> 5;
#pragma unroll
    for (int o = 16; o > 0; o >>= 1) {
        sum += __shfl_xor_sync(0xffffffffu, sum, o);
        sq  += __shfl_xor_sync(0xffffffffu, sq, o);
    }
    if (lane == 0) { sh[w] = sum; sh[8 + w] = sq; }
    __syncthreads();
    float s = 0.f, q = 0.f;
#pragma unroll
    for (int i = 0; i < 8; i++) { s += sh[i]; q += sh[8 + i]; }
    return make_float2(s, q);
}

// ---------------- 1) input LayerNorm (fp16 out) ----------------
__global__ __launch_bounds__(256) void ln_in_kernel(const float* __restrict__ x,
                                                    const float* __restrict__ g,
                                                    const float* __restrict__ be) {
    const int row = blockIdx.x, t = threadIdx.x;
    const float* xr = x + (size_t)row * EE;
    const float2 v = *(const float2*)&xr[2 * t];
    float2 r = block_reduce_sum2(v.x + v.y, v.x * v.x + v.y * v.y);
    float mu = r.x * (1.f / 512.f);
    float var = r.y * (1.f / 512.f) - mu * mu;
    float rs = rsqrtf(var + 1e-6f);
    const float2 gg = *(const float2*)&g[2 * t];
    const float2 bb = *(const float2*)&be[2 * t];
    float y0 = (v.x - mu) * rs * gg.x + bb.x;
    float y1 = (v.y - mu) * rs * gg.y + bb.y;
    ((__half2*)(g_normed + (size_t)row * EE))[t] = __floats2half2_rn(y0, y1);
}

// ---------------- 1b) transpose W [E,FF] -> g_Wt [FF,E] fp16 ----------------
__global__ __launch_bounds__(256) void transpose_w_kernel(const float* __restrict__ W) {
    __shared__ float tile[32][33];
    const int tx = threadIdx.x, ty = threadIdx.y;   // 32 x 8
    const int n0 = blockIdx.x * 32, k0 = blockIdx.y * 32;
#pragma unroll
    for (int j = 0; j < 4; j++)
        tile[ty + j * 8][tx] = W[(size_t)(k0 + ty + j * 8) * FF + n0 + tx];
    __syncthreads();
#pragma unroll
    for (int j = 0; j < 4; j++)
        g_Wt[(size_t)(n0 + ty + j * 8) * EE + k0 + tx] = __float2half(tile[tx][ty + j * 8]);
}

// ---------------- 2) projection GEMM (fp16 mma m16n8k16 + ldmatrix) ----------------
// 128x128 tile, BK=64, 256 threads = 8 warps (2m x 4n), warp tile 64x32
// smem halves: A st: st*9216, B st: 18432 + st*9216; row stride 72 halves (144B)
#define PROJ_SMEM (4 * 128 * 72 * 2)   // 73728 B
__global__ __launch_bounds__(256) void gemm_proj_kernel() {
    extern __shared__ __half sh[];
    const int t = threadIdx.x;
    const int wid = t >> 5, lane = t & 31;
    const int gid = lane >> 2, tig = lane & 3;
    const int warp_m = wid & 1, warp_n = wid >> 1;
    const int m0 = warp_m * 64, n0 = warp_n * 32;
    const int bm = blockIdx.y * 128, bn = blockIdx.x * 128;

    float acc[4][4][4] = {};

#define PJ_LOAD(st, k0) do {                                                           \
        __half* sA = sh + (st) * 9216;                                                 \
        __half* sB = sh + 18432 + (st) * 9216;                                         \
        _Pragma("unroll")                                                              \
        for (int i = 0; i < 4; i++) {                                                  \
            const int gidx = t + i * 256;                                              \
            const int row = gidx >> 3, q = gidx & 7;                                   \
            cpa16(sA + row * 72 + q * 8, &g_normed[(size_t)(bm + row) * EE + (k0) + q * 8]); \
            cpa16(sB + row * 72 + q * 8, &g_Wt[(size_t)(bn + row) * EE + (k0) + q * 8]);    \
        }                                                                              \
    } while (0)

    PJ_LOAD(0, 0); cp_commit();

    for (int it = 0; it < 8; ++it) {
        if (it < 7) { PJ_LOAD((it + 1) & 1, (it + 1) * 64); cp_commit(); cp_wait1(); }
        else cp_wait0();
        __syncthreads();
        const int st = it & 1;
        const uint32_t aBase = smem_u32(sh + st * 9216);
        const uint32_t bBase = smem_u32(sh + 18432 + st * 9216);
#pragma unroll
        for (int ks = 0; ks < 4; ks++) {
            const int k0h = ks * 16;
            uint32_t af[4][4], bf[2][4];
#pragma unroll
            for (int mi = 0; mi < 4; mi++)
                ldsm_x4(af[mi], aBase + (uint32_t)((m0 + mi * 16 + (lane & 15)) * 144
                                                   + (k0h + ((lane >> 4) << 3)) * 2));
#pragma unroll
            for (int p = 0; p < 2; p++) {
                const int row = n0 + p * 16 + (lane & 7) + ((lane >> 4) << 3);
                const int kadd = ((lane >> 3) & 1) << 3;
                ldsm_x4(bf[p], bBase + (uint32_t)(row * 144 + (k0h + kadd) * 2));
            }
#pragma unroll
            for (int mi = 0; mi < 4; mi++)
#pragma unroll
                for (int ni = 0; ni < 4; ni++)
                    mma_f16(acc[mi][ni], af[mi], &bf[ni >> 1][(ni & 1) * 2]);
        }
        __syncthreads();
    }

    // epilogue: U columns (bn<512) -> fp32 g_u; V/Q/K -> fp16 g_qkv
#pragma unroll
    for (int mi = 0; mi < 4; mi++)
#pragma unroll
        for (int ni = 0; ni < 4; ni++) {
            const int r = bm + m0 + mi * 16 + gid;
            const int c = n0 + ni * 8 + 2 * tig;
            if (bn < 512) {
                *(float2*)&g_u[(size_t)r * LH + bn + c]       = make_float2(acc[mi][ni][0], acc[mi][ni][1]);
                *(float2*)&g_u[(size_t)(r + 8) * LH + bn + c] = make_float2(acc[mi][ni][2], acc[mi][ni][3]);
            } else {
                const int qc = bn - 512 + c;
                *(__half2*)&g_qkv[(size_t)r * QKV_W + qc]       = __floats2half2_rn(acc[mi][ni][0], acc[mi][ni][1]);
                *(__half2*)&g_qkv[(size_t)(r + 8) * QKV_W + qc] = __floats2half2_rn(acc[mi][ni][2], acc[mi][ni][3]);
            }
        }
}

// ---------------- 3) causal silu-attention (fp16 mma + ldmatrix) ----------------
// grid (16 q-tiles, 32 b*h), 512 threads = 16 warps (4n x 4m)
// smem halves: qs @0 [128][72], ps @9216 [128][72], ks st @18432+st*4608, vs st @27648+st*4608
#define ATTN_SMEM (4 * 9216 * 2)   // 73728 B
__global__ __launch_bounds__(512) void attn_kernel() {
    extern __shared__ __half sh[];
    __half* qs = sh;
    __half* ps = sh + 9216;

    const int t = threadIdx.x;
    const int wid = t >> 5, lane = t & 31;
    const int gid = lane >> 2, tig = lane & 3;
    const int warp_n = wid >> 2, warp_m = wid & 3;
    const int n0 = warp_n * 32, m0w = warp_m * 16;

    const int nt = 15 - blockIdx.x;     // largest workloads first
    const int bh = blockIdx.y;
    const int b = bh >> 3, h = bh & 7;
    const int nbase = nt << 7;
    const size_t base = (size_t)b * SS;
    const int hd = h << 6;

    const int lrow = t >> 3, lq = t & 7;   // 8 granules (16B) per 64-half row

    // Q tile (128 rows)
#pragma unroll
    for (int i = 0; i < 2; i++) {
        const int row = lrow + i * 64;
        cpa16(qs + row * 72 + lq * 8,
              &g_qkv[(base + nbase + row) * QKV_W + QO_Q + hd + lq * 8]);
    }

#define LOAD_KV_ST(st, m0b) do {                                                        \
        __half* sk = sh + 18432 + (st) * 4608;                                          \
        __half* sv = sh + 27648 + (st) * 4608;                                          \
        const __half* rowp = &g_qkv[(base + (m0b) + lrow) * QKV_W + hd + lq * 8];       \
        cpa16(sk + lrow * 72 + lq * 8, rowp + QO_K);                                    \
        cpa16(sv + lrow * 72 + lq * 8, rowp + QO_V);                                    \
    } while (0)

    LOAD_KV_ST(0, 0); cp_commit();

    float o[2][2][4] = {};
    const int nkt = 2 * nt + 2;

    for (int kt = 0; kt < nkt; ++kt) {
        const int m0b = kt << 6;
        if (kt + 1 < nkt) { LOAD_KV_ST((kt + 1) & 1, (kt + 1) << 6); cp_commit(); cp_wait1(); }
        else cp_wait0();
        __syncthreads();
        const int st = kt & 1;
        const uint32_t kBase = smem_u32(sh + 18432 + st * 4608);
        const uint32_t vBase = smem_u32(sh + 27648 + st * 4608);
        const uint32_t qBase = smem_u32(qs);
        const uint32_t pBase = smem_u32(ps);

        // S = Q @ K^T  (warp: 32n x 16m), K d-major -> non-trans ldmatrix
        float s[2][2][4] = {};
#pragma unroll
        for (int ks = 0; ks < 4; ks++) {
            const int d0h = ks * 16;
            uint32_t aq[2][4], bk[4];
#pragma unroll
            for (int ni = 0; ni < 2; ni++)
                ldsm_x4(aq[ni], qBase + (uint32_t)((n0 + ni * 16 + (lane & 15)) * 144
                                                   + (d0h + ((lane >> 4) << 3)) * 2));
            {
                const int row = m0w + (lane & 7) + ((lane >> 4) << 3);
                const int kadd = ((lane >> 3) & 1) << 3;
                ldsm_x4(bk, kBase + (uint32_t)(row * 144 + (d0h + kadd) * 2));
            }
#pragma unroll
            for (int ni = 0; ni < 2; ni++)
#pragma unroll
                for (int mi = 0; mi < 2; mi++)
                    mma_f16(s[ni][mi], aq[ni], &bk[mi * 2]);
        }

        // silu * causal mask -> ps (fp16)
#pragma unroll
        for (int ni = 0; ni < 2; ni++)
#pragma unroll
            for (int mi = 0; mi < 2; mi++) {
                const int nl = n0 + ni * 16 + gid;
                const int ml = m0w + mi * 8 + 2 * tig;
                float p[4];
#pragma unroll
                for (int cc = 0; cc < 4; cc++) {
                    const int rr = nl + (cc >> 1) * 8;
                    const int mm = ml + (cc & 1);
                    float x = s[ni][mi][cc];
                    float v = x / (1.0f + __expf(-x));
                    p[cc] = (m0b + mm > nbase + rr) ? 0.0f : v;
                }
                *(__half2*)(ps + nl * 72 + ml)       = __floats2half2_rn(p[0], p[1]);
                *(__half2*)(ps + (nl + 8) * 72 + ml) = __floats2half2_rn(p[2], p[3]);
            }
        __syncthreads();

        // O += P @ V  (warp: 32n x 16d), V [m][d] -> trans ldmatrix for B
#pragma unroll
        for (int ks = 0; ks < 4; ks++) {
            const int mk = ks * 16;
            uint32_t ap[2][4], bv[4];
#pragma unroll
            for (int ni = 0; ni < 2; ni++)
                ldsm_x4(ap[ni], pBase + (uint32_t)((n0 + ni * 16 + (lane & 15)) * 144
                                                   + (mk + ((lane >> 4) << 3)) * 2));
            {
                const int row = mk + (lane & 7) + (((lane >> 3) & 1) << 3);
                const int col = m0w + ((lane >> 4) << 3);
                ldsm_x4_t(bv, vBase + (uint32_t)(row * 144 + col * 2));
            }
#pragma unroll
            for (int ni = 0; ni < 2; ni++)
#pragma unroll
                for (int di = 0; di < 2; di++)
                    mma_f16(o[ni][di], ap[ni], &bv[di * 2]);
        }
        __syncthreads();   // protect stage buffers + ps before next iteration
    }

#pragma unroll
    for (int ni = 0; ni < 2; ni++)
#pragma unroll
        for (int di = 0; di < 2; di++) {
            const size_t r = base + nbase + n0 + ni * 16 + gid;
            const int c = hd + m0w + di * 8 + 2 * tig;
            *(float2*)&g_attn[r * LH + c]       = make_float2(o[ni][di][0], o[ni][di][1]);
            *(float2*)&g_attn[(r + 8) * LH + c] = make_float2(o[ni][di][2], o[ni][di][3]);
        }
}

// ---------------- 4) output LN * u + residual ----------------
__global__ __launch_bounds__(256) void out_kernel(const float* __restrict__ ue,
                                                  const float* __restrict__ g,
                                                  const float* __restrict__ be,
                                                  float* __restrict__ out) {
    const int row = blockIdx.x, t = threadIdx.x;
    const float* ar = g_attn + (size_t)row * LH;
    float a0 = ar[t], a1 = ar[t + 256];
    float2 r = block_reduce_sum2(a0 + a1, a0 * a0 + a1 * a1);
    float mu = r.x * (1.f / 512.f);
    float var = r.y * (1.f / 512.f) - mu * mu;
    float rs = rsqrtf(var + 1e-6f);
    const float* ur  = g_u + (size_t)row * LH;
    const float* uer = ue + (size_t)row * EE;
    float* orow = out + (size_t)row * EE;
    orow[t]       = uer[t]       + ((a0 - mu) * rs * g[t]       + be[t])       * ur[t];
    orow[t + 256] = uer[t + 256] + ((a1 - mu) * rs * g[t + 256] + be[t + 256]) * ur[t + 256];
}

extern "C" void kernel_launch(void* const* d_in, const int* in_sizes, int n_in,
                              void* d_out, int out_size) {
    (void)in_sizes; (void)n_in; (void)out_size;
    const float* ue   = (const float*)d_in[0];
    const float* uvqk = (const float*)d_in[2];
    const float* ing  = (const float*)d_in[3];
    const float* inb  = (const float*)d_in[4];
    const float* outg = (const float*)d_in[5];
    const float* outb = (const float*)d_in[6];
    float* out = (float*)d_out;

    cudaFuncSetAttribute(gemm_proj_kernel, cudaFuncAttributeMaxDynamicSharedMemorySize, PROJ_SMEM);
    cudaFuncSetAttribute(attn_kernel, cudaFuncAttributeMaxDynamicSharedMemorySize, ATTN_SMEM);

    ln_in_kernel<<<NROW, 256>>>(ue, ing, inb);
    transpose_w_kernel<<<dim3(FF / 32, EE / 32), dim3(32, 8)>>>(uvqk);
    gemm_proj_kernel<<<dim3(FF / 128, NROW / 128), 256, PROJ_SMEM>>>();
    attn_kernel<<<dim3(SS / 128, BB * HH), 512, ATTN_SMEM>>>();
    out_kernel<<<NROW, 256>>>(ue, outg, outb, out);
}

// round 8
// speedup vs baseline: 1.7392x; 1.0239x over previous
#include <cuda_runtime.h>
#include <cuda_fp16.h>
#include <math.h>
#include <stdint.h>

#define EE 512
#define HH 8
#define BB 4
#define SS 2048
#define NROW (BB*SS)            // 8192
#define FF 2048                 // 2LH + 2AH
#define LH 512

// qkv packed layout per row: V @0, Q @512, K @1024 (halves)
#define QKV_W 1536
#define QO_V 0
#define QO_Q 512
#define QO_K 1024

// Scratch (allocation-free rule: __device__ globals)
__device__ __half g_normed[(size_t)NROW*EE];   // 8.4 MB
__device__ __half g_Wt[(size_t)FF*EE];         // 2 MB (W transposed, fp16)
__device__ __half g_qkv[(size_t)NROW*QKV_W];   // 25 MB (V,Q,K fp16)
__device__ float  g_u[(size_t)NROW*LH];        // 16.8 MB (U fp32)
__device__ float  g_attn[(size_t)NROW*LH];     // 16.8 MB

// ---------------- helpers ----------------
__device__ __forceinline__ uint32_t h2u(__half2 h) {
    uint32_t u;
    memcpy(&u, &h, 4);
    return u;
}
__device__ __forceinline__ void cpa16(void* dst, const void* src) {
    unsigned u = (unsigned)__cvta_generic_to_shared(dst);
    asm volatile("cp.async.cg.shared.global [%0], [%1], 16;\n" :: "r"(u), "l"(src));
}
__device__ __forceinline__ void cp_commit() { asm volatile("cp.async.commit_group;\n"); }
__device__ __forceinline__ void cp_wait0() { asm volatile("cp.async.wait_group 0;\n"); }
__device__ __forceinline__ void cp_wait1() { asm volatile("cp.async.wait_group 1;\n"); }

__device__ __forceinline__ uint32_t smem_u32(const void* p) {
    return (uint32_t)__cvta_generic_to_shared(p);
}
__device__ __forceinline__ void ldsm_x4(uint32_t* r, uint32_t addr) {
    asm volatile("ldmatrix.sync.aligned.m8n8.x4.shared.b16 {%0,%1,%2,%3}, [%4];"
                 : "=r"(r[0]), "=r"(r[1]), "=r"(r[2]), "=r"(r[3]) : "r"(addr));
}
__device__ __forceinline__ void ldsm_x4_t(uint32_t* r, uint32_t addr) {
    asm volatile("ldmatrix.sync.aligned.m8n8.x4.trans.shared.b16 {%0,%1,%2,%3}, [%4];"
                 : "=r"(r[0]), "=r"(r[1]), "=r"(r[2]), "=r"(r[3]) : "r"(addr));
}
__device__ __forceinline__ void mma_f16(float* d, const uint32_t* a, const uint32_t* b) {
    asm volatile(
        "mma.sync.aligned.m16n8k16.row.col.f32.f16.f16.f32 "
        "{%0,%1,%2,%3}, {%4,%5,%6,%7}, {%8,%9}, {%0,%1,%2,%3};\n"
        : "+f"(d[0]), "+f"(d[1]), "+f"(d[2]), "+f"(d[3])
        : "r"(a[0]), "r"(a[1]), "r"(a[2]), "r"(a[3]), "r"(b[0]), "r"(b[1]));
}

__device__ __forceinline__ float2 block_reduce_sum2(float sum, float sq) {
    __shared__ float sh[16];
    int lane = threadIdx.x & 31, w = threadIdx.x >> 5;
#pragma unroll
    for (int o = 16; o > 0; o >>= 1) {
        sum += __shfl_xor_sync(0xffffffffu, sum, o);
        sq  += __shfl_xor_sync(0xffffffffu, sq, o);
    }
    if (lane == 0) { sh[w] = sum; sh[8 + w] = sq; }
    __syncthreads();
    float s = 0.f, q = 0.f;
#pragma unroll
    for (int i = 0; i < 8; i++) { s += sh[i]; q += sh[8 + i]; }
    return make_float2(s, q);
}

// ---------------- 1) input LayerNorm (fp16 out) ----------------
__global__ __launch_bounds__(256) void ln_in_kernel(const float* __restrict__ x,
                                                    const float* __restrict__ g,
                                                    const float* __restrict__ be) {
    const int row = blockIdx.x, t = threadIdx.x;
    const float* xr = x + (size_t)row * EE;
    const float2 v = *(const float2*)&xr[2 * t];
    float2 r = block_reduce_sum2(v.x + v.y, v.x * v.x + v.y * v.y);
    float mu = r.x * (1.f / 512.f);
    float var = r.y * (1.f / 512.f) - mu * mu;
    float rs = rsqrtf(var + 1e-6f);
    const float2 gg = *(const float2*)&g[2 * t];
    const float2 bb = *(const float2*)&be[2 * t];
    float y0 = (v.x - mu) * rs * gg.x + bb.x;
    float y1 = (v.y - mu) * rs * gg.y + bb.y;
    ((__half2*)(g_normed + (size_t)row * EE))[t] = __floats2half2_rn(y0, y1);
}

// ---------------- 1b) transpose W [E,FF] -> g_Wt [FF,E] fp16 ----------------
__global__ __launch_bounds__(256) void transpose_w_kernel(const float* __restrict__ W) {
    __shared__ float tile[32][33];
    const int tx = threadIdx.x, ty = threadIdx.y;   // 32 x 8
    const int n0 = blockIdx.x * 32, k0 = blockIdx.y * 32;
#pragma unroll
    for (int j = 0; j < 4; j++)
        tile[ty + j * 8][tx] = W[(size_t)(k0 + ty + j * 8) * FF + n0 + tx];
    __syncthreads();
#pragma unroll
    for (int j = 0; j < 4; j++)
        g_Wt[(size_t)(n0 + ty + j * 8) * EE + k0 + tx] = __float2half(tile[tx][ty + j * 8]);
}

// ---------------- 2) projection GEMM (fp16 mma m16n8k16 + ldmatrix) ----------------
// 128x128 tile, BK=64, 256 threads = 8 warps (2m x 4n), warp tile 64x32
#define PROJ_SMEM (4 * 128 * 72 * 2)   // 73728 B
__global__ __launch_bounds__(256) void gemm_proj_kernel() {
    extern __shared__ __half sh[];
    const int t = threadIdx.x;
    const int wid = t >> 5, lane = t & 31;
    const int gid = lane >> 2, tig = lane & 3;
    const int warp_m = wid & 1, warp_n = wid >> 1;
    const int m0 = warp_m * 64, n0 = warp_n * 32;
    const int bm = blockIdx.y * 128, bn = blockIdx.x * 128;

    float acc[4][4][4] = {};

#define PJ_LOAD(st, k0) do {                                                           \
        __half* sA = sh + (st) * 9216;                                                 \
        __half* sB = sh + 18432 + (st) * 9216;                                         \
        _Pragma("unroll")                                                              \
        for (int i = 0; i < 4; i++) {                                                  \
            const int gidx = t + i * 256;                                              \
            const int row = gidx >> 3, q = gidx & 7;                                   \
            cpa16(sA + row * 72 + q * 8, &g_normed[(size_t)(bm + row) * EE + (k0) + q * 8]); \
            cpa16(sB + row * 72 + q * 8, &g_Wt[(size_t)(bn + row) * EE + (k0) + q * 8]);    \
        }                                                                              \
    } while (0)

    PJ_LOAD(0, 0); cp_commit();

    for (int it = 0; it < 8; ++it) {
        if (it < 7) { PJ_LOAD((it + 1) & 1, (it + 1) * 64); cp_commit(); cp_wait1(); }
        else cp_wait0();
        __syncthreads();
        const int st = it & 1;
        const uint32_t aBase = smem_u32(sh + st * 9216);
        const uint32_t bBase = smem_u32(sh + 18432 + st * 9216);
#pragma unroll
        for (int ks = 0; ks < 4; ks++) {
            const int k0h = ks * 16;
            uint32_t af[4][4], bf[2][4];
#pragma unroll
            for (int mi = 0; mi < 4; mi++)
                ldsm_x4(af[mi], aBase + (uint32_t)((m0 + mi * 16 + (lane & 15)) * 144
                                                   + (k0h + ((lane >> 4) << 3)) * 2));
#pragma unroll
            for (int p = 0; p < 2; p++) {
                const int row = n0 + p * 16 + (lane & 7) + ((lane >> 4) << 3);
                const int kadd = ((lane >> 3) & 1) << 3;
                ldsm_x4(bf[p], bBase + (uint32_t)(row * 144 + (k0h + kadd) * 2));
            }
#pragma unroll
            for (int mi = 0; mi < 4; mi++)
#pragma unroll
                for (int ni = 0; ni < 4; ni++)
                    mma_f16(acc[mi][ni], af[mi], &bf[ni >> 1][(ni & 1) * 2]);
        }
        __syncthreads();
    }

    // epilogue: U columns (bn<512) -> fp32 g_u; V/Q/K -> fp16 g_qkv
#pragma unroll
    for (int mi = 0; mi < 4; mi++)
#pragma unroll
        for (int ni = 0; ni < 4; ni++) {
            const int r = bm + m0 + mi * 16 + gid;
            const int c = n0 + ni * 8 + 2 * tig;
            if (bn < 512) {
                *(float2*)&g_u[(size_t)r * LH + bn + c]       = make_float2(acc[mi][ni][0], acc[mi][ni][1]);
                *(float2*)&g_u[(size_t)(r + 8) * LH + bn + c] = make_float2(acc[mi][ni][2], acc[mi][ni][3]);
            } else {
                const int qc = bn - 512 + c;
                *(__half2*)&g_qkv[(size_t)r * QKV_W + qc]       = __floats2half2_rn(acc[mi][ni][0], acc[mi][ni][1]);
                *(__half2*)&g_qkv[(size_t)(r + 8) * QKV_W + qc] = __floats2half2_rn(acc[mi][ni][2], acc[mi][ni][3]);
            }
        }
}

// ---------------- 3) causal silu-attention: FA2-style, register-resident P ----------------
// grid (16 q-tiles, 32 b*h), 256 threads = 8 warps, warp owns 16 q-rows x full 64-col K tile.
// smem (halves): qs [128][72] @0; 3-stage KV ring @9216: stage st: K @9216+st*9216, V +4608.
#define ATTN_SMEM ((9216 + 3 * 9216) * 2)   // 73728 B
__global__ __launch_bounds__(256, 2) void attn_kernel() {
    extern __shared__ __half sh[];
    __half* qs = sh;

    const int t = threadIdx.x;
    const int wid = t >> 5, lane = t & 31;
    const int gid = lane >> 2, tig = lane & 3;

    const int nt = 15 - blockIdx.x;     // largest workloads first
    const int bh = blockIdx.y;
    const int b = bh >> 3, h = bh & 7;
    const int nbase = nt << 7;
    const size_t base = (size_t)b * SS;
    const int hd = h << 6;

    const int qrow = wid * 16;                  // warp's local Q-row base
    const int grow = nbase + qrow + gid;        // global row of accum frag (row 0 half)

    const int lrow = t >> 3, lq = t & 7;        // loaders

    // Q tile (128 rows) — same commit group as stage 0
#pragma unroll
    for (int i = 0; i < 4; i++) {
        const int row = lrow + i * 32;
        cpa16(qs + row * 72 + lq * 8,
              &g_qkv[(base + nbase + row) * QKV_W + QO_Q + hd + lq * 8]);
    }

#define LOAD_KV_ST(st, m0b) do {                                                        \
        __half* sk = sh + 9216 + (st) * 9216;                                           \
        __half* sv = sk + 4608;                                                         \
        _Pragma("unroll")                                                               \
        for (int i = 0; i < 2; i++) {                                                   \
            const int row = lrow + i * 32;                                              \
            const __half* rowp = &g_qkv[(base + (m0b) + row) * QKV_W + hd + lq * 8];    \
            cpa16(sk + row * 72 + lq * 8, rowp + QO_K);                                 \
            cpa16(sv + row * 72 + lq * 8, rowp + QO_V);                                 \
        }                                                                               \
    } while (0)

    const int nkt = 2 * nt + 2;
    LOAD_KV_ST(0, 0); cp_commit();
    LOAD_KV_ST(1, (nkt > 1 ? 1 : 0) << 6); cp_commit();

    uint32_t aq[4][4];          // Q fragments, resident across loop
    float o[8][4] = {};

    for (int kt = 0; kt < nkt; ++kt) {
        cp_wait1();
        __syncthreads();
        // prefetch kt+2 into stage (kt+2)%3 (clamped; (kt+2)%3 != kt%3)
        {
            const int it2 = (kt + 2 < nkt) ? kt + 2 : nkt - 1;
            LOAD_KV_ST((kt + 2) % 3, it2 << 6);
            cp_commit();
        }
        if (kt == 0) {
#pragma unroll
            for (int ks = 0; ks < 4; ks++)
                ldsm_x4(aq[ks], smem_u32(qs) +
                        (uint32_t)((qrow + (lane & 15)) * 144 + (ks * 16 + ((lane >> 4) << 3)) * 2));
        }
        const int st = kt % 3;
        const uint32_t kBase = smem_u32(sh + 9216 + st * 9216);
        const uint32_t vBase = kBase + 9216;    // +4608 halves
        const int m0b = kt << 6;

        // ---- S = Q(16x64) @ K^T(64x64) ----
        float s[8][4] = {};
#pragma unroll
        for (int ks = 0; ks < 4; ks++) {
            const int d0h = ks * 16;
            uint32_t bk[4][4];
#pragma unroll
            for (int p = 0; p < 4; p++) {
                const int row = p * 16 + (lane & 7) + ((lane >> 4) << 3);
                const int kadd = ((lane >> 3) & 1) << 3;
                ldsm_x4(bk[p], kBase + (uint32_t)(row * 144 + (d0h + kadd) * 2));
            }
#pragma unroll
            for (int nb = 0; nb < 8; nb++)
                mma_f16(s[nb], aq[ks], &bk[nb >> 1][(nb & 1) * 2]);
        }

        // ---- silu + causal mask -> fp16 A-fragments (registers only) ----
        uint32_t pf[4][4];
#pragma unroll
        for (int nb = 0; nb < 8; nb++) {
            const int mmb = m0b + nb * 8 + 2 * tig;
#pragma unroll
            for (int cc = 0; cc < 4; cc++) {
                const int rr = grow + ((cc >> 1) << 3);
                const int mm = mmb + (cc & 1);
                float x = s[nb][cc];
                float v = x / (1.0f + __expf(-x));
                s[nb][cc] = (mm > rr) ? 0.0f : v;
            }
        }
#pragma unroll
        for (int kb = 0; kb < 4; kb++) {
            pf[kb][0] = h2u(__floats2half2_rn(s[2*kb][0],   s[2*kb][1]));
            pf[kb][1] = h2u(__floats2half2_rn(s[2*kb][2],   s[2*kb][3]));
            pf[kb][2] = h2u(__floats2half2_rn(s[2*kb+1][0], s[2*kb+1][1]));
            pf[kb][3] = h2u(__floats2half2_rn(s[2*kb+1][2], s[2*kb+1][3]));
        }

        // ---- O += P(16x64) @ V(64x64) ----
#pragma unroll
        for (int kb = 0; kb < 4; kb++) {
            const int mk = kb * 16;
            uint32_t bv[4][4];
#pragma unroll
            for (int db = 0; db < 4; db++) {
                const int row = mk + (lane & 7) + (((lane >> 3) & 1) << 3);
                const int col = db * 16 + ((lane >> 4) << 3);
                ldsm_x4_t(bv[db], vBase + (uint32_t)(row * 144 + col * 2));
            }
#pragma unroll
            for (int dnb = 0; dnb < 8; dnb++)
                mma_f16(o[dnb], pf[kb], &bv[dnb >> 1][(dnb & 1) * 2]);
        }
    }

    // ---- write O ----
#pragma unroll
    for (int dnb = 0; dnb < 8; dnb++) {
        const size_t r = base + grow;
        const int c = hd + dnb * 8 + 2 * tig;
        *(float2*)&g_attn[r * LH + c]       = make_float2(o[dnb][0], o[dnb][1]);
        *(float2*)&g_attn[(r + 8) * LH + c] = make_float2(o[dnb][2], o[dnb][3]);
    }
}

// ---------------- 4) output LN * u + residual ----------------
__global__ __launch_bounds__(256) void out_kernel(const float* __restrict__ ue,
                                                  const float* __restrict__ g,
                                                  const float* __restrict__ be,
                                                  float* __restrict__ out) {
    const int row = blockIdx.x, t = threadIdx.x;
    const float* ar = g_attn + (size_t)row * LH;
    float a0 = ar[t], a1 = ar[t + 256];
    float2 r = block_reduce_sum2(a0 + a1, a0 * a0 + a1 * a1);
    float mu = r.x * (1.f / 512.f);
    float var = r.y * (1.f / 512.f) - mu * mu;
    float rs = rsqrtf(var + 1e-6f);
    const float* ur  = g_u + (size_t)row * LH;
    const float* uer = ue + (size_t)row * EE;
    float* orow = out + (size_t)row * EE;
    orow[t]       = uer[t]       + ((a0 - mu) * rs * g[t]       + be[t])       * ur[t];
    orow[t + 256] = uer[t + 256] + ((a1 - mu) * rs * g[t + 256] + be[t + 256]) * ur[t + 256];
}

extern "C" void kernel_launch(void* const* d_in, const int* in_sizes, int n_in,
                              void* d_out, int out_size) {
    (void)in_sizes; (void)n_in; (void)out_size;
    const float* ue   = (const float*)d_in[0];
    const float* uvqk = (const float*)d_in[2];
    const float* ing  = (const float*)d_in[3];
    const float* inb  = (const float*)d_in[4];
    const float* outg = (const float*)d_in[5];
    const float* outb = (const float*)d_in[6];
    float* out = (float*)d_out;

    cudaFuncSetAttribute(gemm_proj_kernel, cudaFuncAttributeMaxDynamicSharedMemorySize, PROJ_SMEM);
    cudaFuncSetAttribute(attn_kernel, cudaFuncAttributeMaxDynamicSharedMemorySize, ATTN_SMEM);

    ln_in_kernel<<<NROW, 256>>>(ue, ing, inb);
    transpose_w_kernel<<<dim3(FF / 32, EE / 32), dim3(32, 8)>>>(uvqk);
    gemm_proj_kernel<<<dim3(FF / 128, NROW / 128), 256, PROJ_SMEM>>>();
    attn_kernel<<<dim3(SS / 128, BB * HH), 256, ATTN_SMEM>>>();
    out_kernel<<<NROW, 256>>>(ue, outg, outb, out);
}

// round 9
// speedup vs baseline: 2.4838x; 1.4282x over previous
#include <cuda_runtime.h>
#include <cuda_fp16.h>
#include <math.h>
#include <stdint.h>

#define EE 512
#define HH 8
#define BB 4
#define SS 2048
#define NROW (BB*SS)            // 8192
#define FF 2048                 // 2LH + 2AH
#define LH 512

// qkv packed layout per row: V @0, Q @512, K @1024 (halves)
#define QKV_W 1536
#define QO_V 0
#define QO_Q 512
#define QO_K 1024

// Scratch (allocation-free rule: __device__ globals)
__device__ __half g_normed[(size_t)NROW*EE];   // 8.4 MB
__device__ __half g_Wt[(size_t)FF*EE];         // 2 MB (W transposed, fp16)
__device__ __half g_qkv[(size_t)NROW*QKV_W];   // 25 MB (V,Q,K fp16)
__device__ float  g_u[(size_t)NROW*LH];        // 16.8 MB (U fp32)
__device__ float  g_attn[(size_t)NROW*LH];     // 16.8 MB

// ---------------- helpers ----------------
__device__ __forceinline__ uint32_t h2u(__half2 h) {
    uint32_t u;
    memcpy(&u, &h, 4);
    return u;
}
__device__ __forceinline__ float silu_fast(float x) {
    // silu(x) = 0.5x(1 + tanh(x/2)); tanh.approx saturates exactly -> exact tails
    float th;
    asm("tanh.approx.f32 %0, %1;" : "=f"(th) : "f"(0.5f * x));
    return 0.5f * x * (1.0f + th);
}
__device__ __forceinline__ void cpa16(void* dst, const void* src) {
    unsigned u = (unsigned)__cvta_generic_to_shared(dst);
    asm volatile("cp.async.cg.shared.global [%0], [%1], 16;\n" :: "r"(u), "l"(src));
}
__device__ __forceinline__ void cp_commit() { asm volatile("cp.async.commit_group;\n"); }
__device__ __forceinline__ void cp_wait0() { asm volatile("cp.async.wait_group 0;\n"); }
__device__ __forceinline__ void cp_wait1() { asm volatile("cp.async.wait_group 1;\n"); }

__device__ __forceinline__ uint32_t smem_u32(const void* p) {
    return (uint32_t)__cvta_generic_to_shared(p);
}
__device__ __forceinline__ void ldsm_x4(uint32_t* r, uint32_t addr) {
    asm volatile("ldmatrix.sync.aligned.m8n8.x4.shared.b16 {%0,%1,%2,%3}, [%4];"
                 : "=r"(r[0]), "=r"(r[1]), "=r"(r[2]), "=r"(r[3]) : "r"(addr));
}
__device__ __forceinline__ void ldsm_x4_t(uint32_t* r, uint32_t addr) {
    asm volatile("ldmatrix.sync.aligned.m8n8.x4.trans.shared.b16 {%0,%1,%2,%3}, [%4];"
                 : "=r"(r[0]), "=r"(r[1]), "=r"(r[2]), "=r"(r[3]) : "r"(addr));
}
__device__ __forceinline__ void mma_f16(float* d, const uint32_t* a, const uint32_t* b) {
    asm volatile(
        "mma.sync.aligned.m16n8k16.row.col.f32.f16.f16.f32 "
        "{%0,%1,%2,%3}, {%4,%5,%6,%7}, {%8,%9}, {%0,%1,%2,%3};\n"
        : "+f"(d[0]), "+f"(d[1]), "+f"(d[2]), "+f"(d[3])
        : "r"(a[0]), "r"(a[1]), "r"(a[2]), "r"(a[3]), "r"(b[0]), "r"(b[1]));
}

__device__ __forceinline__ float2 block_reduce_sum2(float sum, float sq) {
    __shared__ float sh[16];
    int lane = threadIdx.x & 31, w = threadIdx.x >> 5;
#pragma unroll
    for (int o = 16; o > 0; o >>= 1) {
        sum += __shfl_xor_sync(0xffffffffu, sum, o);
        sq  += __shfl_xor_sync(0xffffffffu, sq, o);
    }
    if (lane == 0) { sh[w] = sum; sh[8 + w] = sq; }
    __syncthreads();
    float s = 0.f, q = 0.f;
#pragma unroll
    for (int i = 0; i < 8; i++) { s += sh[i]; q += sh[8 + i]; }
    return make_float2(s, q);
}

// ---------------- 1) input LayerNorm (fp16 out) ----------------
__global__ __launch_bounds__(256) void ln_in_kernel(const float* __restrict__ x,
                                                    const float* __restrict__ g,
                                                    const float* __restrict__ be) {
    const int row = blockIdx.x, t = threadIdx.x;
    const float* xr = x + (size_t)row * EE;
    const float2 v = *(const float2*)&xr[2 * t];
    float2 r = block_reduce_sum2(v.x + v.y, v.x * v.x + v.y * v.y);
    float mu = r.x * (1.f / 512.f);
    float var = r.y * (1.f / 512.f) - mu * mu;
    float rs = rsqrtf(var + 1e-6f);
    const float2 gg = *(const float2*)&g[2 * t];
    const float2 bb = *(const float2*)&be[2 * t];
    float y0 = (v.x - mu) * rs * gg.x + bb.x;
    float y1 = (v.y - mu) * rs * gg.y + bb.y;
    ((__half2*)(g_normed + (size_t)row * EE))[t] = __floats2half2_rn(y0, y1);
}

// ---------------- 1b) transpose W [E,FF] -> g_Wt [FF,E] fp16 ----------------
__global__ __launch_bounds__(256) void transpose_w_kernel(const float* __restrict__ W) {
    __shared__ float tile[32][33];
    const int tx = threadIdx.x, ty = threadIdx.y;   // 32 x 8
    const int n0 = blockIdx.x * 32, k0 = blockIdx.y * 32;
#pragma unroll
    for (int j = 0; j < 4; j++)
        tile[ty + j * 8][tx] = W[(size_t)(k0 + ty + j * 8) * FF + n0 + tx];
    __syncthreads();
#pragma unroll
    for (int j = 0; j < 4; j++)
        g_Wt[(size_t)(n0 + ty + j * 8) * EE + k0 + tx] = __float2half(tile[tx][ty + j * 8]);
}

// ---------------- 2) projection GEMM (fp16 mma m16n8k16 + ldmatrix) ----------------
// 128x128 tile, BK=64, 256 threads = 8 warps (2m x 4n), warp tile 64x32
#define PROJ_SMEM (4 * 128 * 72 * 2)   // 73728 B
__global__ __launch_bounds__(256) void gemm_proj_kernel() {
    extern __shared__ __half sh[];
    const int t = threadIdx.x;
    const int wid = t >> 5, lane = t & 31;
    const int gid = lane >> 2, tig = lane & 3;
    const int warp_m = wid & 1, warp_n = wid >> 1;
    const int m0 = warp_m * 64, n0 = warp_n * 32;
    const int bm = blockIdx.y * 128, bn = blockIdx.x * 128;

    float acc[4][4][4] = {};

#define PJ_LOAD(st, k0) do {                                                           \
        __half* sA = sh + (st) * 9216;                                                 \
        __half* sB = sh + 18432 + (st) * 9216;                                         \
        _Pragma("unroll")                                                              \
        for (int i = 0; i < 4; i++) {                                                  \
            const int gidx = t + i * 256;                                              \
            const int row = gidx >> 3, q = gidx & 7;                                   \
            cpa16(sA + row * 72 + q * 8, &g_normed[(size_t)(bm + row) * EE + (k0) + q * 8]); \
            cpa16(sB + row * 72 + q * 8, &g_Wt[(size_t)(bn + row) * EE + (k0) + q * 8]);    \
        }                                                                              \
    } while (0)

    PJ_LOAD(0, 0); cp_commit();

    for (int it = 0; it < 8; ++it) {
        if (it < 7) { PJ_LOAD((it + 1) & 1, (it + 1) * 64); cp_commit(); cp_wait1(); }
        else cp_wait0();
        __syncthreads();
        const int st = it & 1;
        const uint32_t aBase = smem_u32(sh + st * 9216);
        const uint32_t bBase = smem_u32(sh + 18432 + st * 9216);
#pragma unroll
        for (int ks = 0; ks < 4; ks++) {
            const int k0h = ks * 16;
            uint32_t af[4][4], bf[2][4];
#pragma unroll
            for (int mi = 0; mi < 4; mi++)
                ldsm_x4(af[mi], aBase + (uint32_t)((m0 + mi * 16 + (lane & 15)) * 144
                                                   + (k0h + ((lane >> 4) << 3)) * 2));
#pragma unroll
            for (int p = 0; p < 2; p++) {
                const int row = n0 + p * 16 + (lane & 7) + ((lane >> 4) << 3);
                const int kadd = ((lane >> 3) & 1) << 3;
                ldsm_x4(bf[p], bBase + (uint32_t)(row * 144 + (k0h + kadd) * 2));
            }
#pragma unroll
            for (int mi = 0; mi < 4; mi++)
#pragma unroll
                for (int ni = 0; ni < 4; ni++)
                    mma_f16(acc[mi][ni], af[mi], &bf[ni >> 1][(ni & 1) * 2]);
        }
        __syncthreads();
    }

    // epilogue: U columns (bn<512) -> fp32 g_u; V/Q/K -> fp16 g_qkv
#pragma unroll
    for (int mi = 0; mi < 4; mi++)
#pragma unroll
        for (int ni = 0; ni < 4; ni++) {
            const int r = bm + m0 + mi * 16 + gid;
            const int c = n0 + ni * 8 + 2 * tig;
            if (bn < 512) {
                *(float2*)&g_u[(size_t)r * LH + bn + c]       = make_float2(acc[mi][ni][0], acc[mi][ni][1]);
                *(float2*)&g_u[(size_t)(r + 8) * LH + bn + c] = make_float2(acc[mi][ni][2], acc[mi][ni][3]);
            } else {
                const int qc = bn - 512 + c;
                *(__half2*)&g_qkv[(size_t)r * QKV_W + qc]       = __floats2half2_rn(acc[mi][ni][0], acc[mi][ni][1]);
                *(__half2*)&g_qkv[(size_t)(r + 8) * QKV_W + qc] = __floats2half2_rn(acc[mi][ni][2], acc[mi][ni][3]);
            }
        }
}

// ---------------- 3) causal silu-attention: FA2-style, register-resident P ----------------
// grid (16 q-tiles, 32 b*h), 256 threads = 8 warps, warp owns 16 q-rows x full 64-col K tile.
// smem (halves): qs [128][72] @0; 3-stage KV ring @9216: stage st: K @9216+st*9216, V +4608.
#define ATTN_SMEM ((9216 + 3 * 9216) * 2)   // 73728 B
__global__ __launch_bounds__(256, 2) void attn_kernel() {
    extern __shared__ __half sh[];
    __half* qs = sh;

    const int t = threadIdx.x;
    const int wid = t >> 5, lane = t & 31;
    const int gid = lane >> 2, tig = lane & 3;

    const int nt = 15 - blockIdx.x;     // largest workloads first
    const int bh = blockIdx.y;
    const int b = bh >> 3, h = bh & 7;
    const int nbase = nt << 7;
    const size_t base = (size_t)b * SS;
    const int hd = h << 6;

    const int qrow = wid * 16;                  // warp's local Q-row base
    const int grow = nbase + qrow + gid;        // global row of accum frag (row 0 half)

    const int lrow = t >> 3, lq = t & 7;        // loaders

    // Q tile (128 rows) — same commit group as stage 0
#pragma unroll
    for (int i = 0; i < 4; i++) {
        const int row = lrow + i * 32;
        cpa16(qs + row * 72 + lq * 8,
              &g_qkv[(base + nbase + row) * QKV_W + QO_Q + hd + lq * 8]);
    }

#define LOAD_KV_ST(st, m0b) do {                                                        \
        __half* sk = sh + 9216 + (st) * 9216;                                           \
        __half* sv = sk + 4608;                                                         \
        _Pragma("unroll")                                                               \
        for (int i = 0; i < 2; i++) {                                                   \
            const int row = lrow + i * 32;                                              \
            const __half* rowp = &g_qkv[(base + (m0b) + row) * QKV_W + hd + lq * 8];    \
            cpa16(sk + row * 72 + lq * 8, rowp + QO_K);                                 \
            cpa16(sv + row * 72 + lq * 8, rowp + QO_V);                                 \
        }                                                                               \
    } while (0)

    const int nkt = 2 * nt + 2;
    LOAD_KV_ST(0, 0); cp_commit();
    LOAD_KV_ST(1, (nkt > 1 ? 1 : 0) << 6); cp_commit();

    uint32_t aq[4][4];          // Q fragments, resident across loop
    float o[8][4] = {};

    for (int kt = 0; kt < nkt; ++kt) {
        cp_wait1();
        __syncthreads();
        // prefetch kt+2 into stage (kt+2)%3 (clamped; (kt+2)%3 != kt%3)
        {
            const int it2 = (kt + 2 < nkt) ? kt + 2 : nkt - 1;
            LOAD_KV_ST((kt + 2) % 3, it2 << 6);
            cp_commit();
        }
        if (kt == 0) {
#pragma unroll
            for (int ks = 0; ks < 4; ks++)
                ldsm_x4(aq[ks], smem_u32(qs) +
                        (uint32_t)((qrow + (lane & 15)) * 144 + (ks * 16 + ((lane >> 4) << 3)) * 2));
        }
        const int st = kt % 3;
        const uint32_t kBase = smem_u32(sh + 9216 + st * 9216);
        const uint32_t vBase = kBase + 9216;    // +4608 halves
        const int m0b = kt << 6;

        // ---- S = Q(16x64) @ K^T(64x64) ----
        float s[8][4] = {};
#pragma unroll
        for (int ks = 0; ks < 4; ks++) {
            const int d0h = ks * 16;
            uint32_t bk[4][4];
#pragma unroll
            for (int p = 0; p < 4; p++) {
                const int row = p * 16 + (lane & 7) + ((lane >> 4) << 3);
                const int kadd = ((lane >> 3) & 1) << 3;
                ldsm_x4(bk[p], kBase + (uint32_t)(row * 144 + (d0h + kadd) * 2));
            }
#pragma unroll
            for (int nb = 0; nb < 8; nb++)
                mma_f16(s[nb], aq[ks], &bk[nb >> 1][(nb & 1) * 2]);
        }

        // ---- silu (tanh.approx) + causal mask -> fp16 A-fragments (registers only) ----
        uint32_t pf[4][4];
#pragma unroll
        for (int nb = 0; nb < 8; nb++) {
            const int mmb = m0b + nb * 8 + 2 * tig;
#pragma unroll
            for (int cc = 0; cc < 4; cc++) {
                const int rr = grow + ((cc >> 1) << 3);
                const int mm = mmb + (cc & 1);
                float v = silu_fast(s[nb][cc]);
                s[nb][cc] = (mm > rr) ? 0.0f : v;
            }
        }
#pragma unroll
        for (int kb = 0; kb < 4; kb++) {
            pf[kb][0] = h2u(__floats2half2_rn(s[2*kb][0],   s[2*kb][1]));
            pf[kb][1] = h2u(__floats2half2_rn(s[2*kb][2],   s[2*kb][3]));
            pf[kb][2] = h2u(__floats2half2_rn(s[2*kb+1][0], s[2*kb+1][1]));
            pf[kb][3] = h2u(__floats2half2_rn(s[2*kb+1][2], s[2*kb+1][3]));
        }

        // ---- O += P(16x64) @ V(64x64) ----
#pragma unroll
        for (int kb = 0; kb < 4; kb++) {
            const int mk = kb * 16;
            uint32_t bv[4][4];
#pragma unroll
            for (int db = 0; db < 4; db++) {
                const int row = mk + (lane & 7) + (((lane >> 3) & 1) << 3);
                const int col = db * 16 + ((lane >> 4) << 3);
                ldsm_x4_t(bv[db], vBase + (uint32_t)(row * 144 + col * 2));
            }
#pragma unroll
            for (int dnb = 0; dnb < 8; dnb++)
                mma_f16(o[dnb], pf[kb], &bv[dnb >> 1][(dnb & 1) * 2]);
        }
    }

    // ---- write O ----
#pragma unroll
    for (int dnb = 0; dnb < 8; dnb++) {
        const size_t r = base + grow;
        const int c = hd + dnb * 8 + 2 * tig;
        *(float2*)&g_attn[r * LH + c]       = make_float2(o[dnb][0], o[dnb][1]);
        *(float2*)&g_attn[(r + 8) * LH + c] = make_float2(o[dnb][2], o[dnb][3]);
    }
}

// ---------------- 4) output LN * u + residual ----------------
__global__ __launch_bounds__(256) void out_kernel(const float* __restrict__ ue,
                                                  const float* __restrict__ g,
                                                  const float* __restrict__ be,
                                                  float* __restrict__ out) {
    const int row = blockIdx.x, t = threadIdx.x;
    const float* ar = g_attn + (size_t)row * LH;
    float a0 = ar[t], a1 = ar[t + 256];
    float2 r = block_reduce_sum2(a0 + a1, a0 * a0 + a1 * a1);
    float mu = r.x * (1.f / 512.f);
    float var = r.y * (1.f / 512.f) - mu * mu;
    float rs = rsqrtf(var + 1e-6f);
    const float* ur  = g_u + (size_t)row * LH;
    const float* uer = ue + (size_t)row * EE;
    float* orow = out + (size_t)row * EE;
    orow[t]       = uer[t]       + ((a0 - mu) * rs * g[t]       + be[t])       * ur[t];
    orow[t + 256] = uer[t + 256] + ((a1 - mu) * rs * g[t + 256] + be[t + 256]) * ur[t + 256];
}

extern "C" void kernel_launch(void* const* d_in, const int* in_sizes, int n_in,
                              void* d_out, int out_size) {
    (void)in_sizes; (void)n_in; (void)out_size;
    const float* ue   = (const float*)d_in[0];
    const float* uvqk = (const float*)d_in[2];
    const float* ing  = (const float*)d_in[3];
    const float* inb  = (const float*)d_in[4];
    const float* outg = (const float*)d_in[5];
    const float* outb = (const float*)d_in[6];
    float* out = (float*)d_out;

    cudaFuncSetAttribute(gemm_proj_kernel, cudaFuncAttributeMaxDynamicSharedMemorySize, PROJ_SMEM);
    cudaFuncSetAttribute(attn_kernel, cudaFuncAttributeMaxDynamicSharedMemorySize, ATTN_SMEM);

    ln_in_kernel<<<NROW, 256>>>(ue, ing, inb);
    transpose_w_kernel<<<dim3(FF / 32, EE / 32), dim3(32, 8)>>>(uvqk);
    gemm_proj_kernel<<<dim3(FF / 128, NROW / 128), 256, PROJ_SMEM>>>();
    attn_kernel<<<dim3(SS / 128, BB * HH), 256, ATTN_SMEM>>>();
    out_kernel<<<NROW, 256>>>(ue, outg, outb, out);
}

// round 10
// speedup vs baseline: 2.8433x; 1.1447x over previous
#include <cuda_runtime.h>
#include <cuda_fp16.h>
#include <math.h>
#include <stdint.h>

#define EE 512
#define HH 8
#define BB 4
#define SS 2048
#define NROW (BB*SS)            // 8192
#define FF 2048                 // 2LH + 2AH
#define LH 512

// qkv packed layout per row: V @0, Q @512, K @1024 (halves)
#define QKV_W 1536
#define QO_V 0
#define QO_Q 512
#define QO_K 1024

// Scratch (allocation-free rule: __device__ globals)
__device__ __half g_normed[(size_t)NROW*EE];   // 8.4 MB
__device__ __half g_Wt[(size_t)FF*EE];         // 2 MB (W transposed, fp16)
__device__ __half g_qkv[(size_t)NROW*QKV_W];   // 25 MB (V,Q,K fp16)
__device__ float  g_u[(size_t)NROW*LH];        // 16.8 MB (U fp32)
__device__ float  g_attn[(size_t)NROW*LH];     // 16.8 MB

// ---------------- helpers ----------------
__device__ __forceinline__ uint32_t h2u(__half2 h) {
    uint32_t u;
    memcpy(&u, &h, 4);
    return u;
}
// silu on packed half2: y = 0.5x + 0.5x*tanh(0.5x)  (exact tails via tanh saturation)
__device__ __forceinline__ uint32_t silu2(uint32_t x2) {
    __half2 x;
    memcpy(&x, &x2, 4);
    __half2 hx = __hmul2(x, __half2half2(__float2half(0.5f)));
    uint32_t hxu = h2u(hx), thu;
    asm("tanh.approx.f16x2 %0, %1;" : "=r"(thu) : "r"(hxu));
    __half2 th;
    memcpy(&th, &thu, 4);
    __half2 y = __hfma2(hx, th, hx);
    return h2u(y);
}
__device__ __forceinline__ void cpa16(void* dst, const void* src) {
    unsigned u = (unsigned)__cvta_generic_to_shared(dst);
    asm volatile("cp.async.cg.shared.global [%0], [%1], 16;\n" :: "r"(u), "l"(src));
}
__device__ __forceinline__ void cp_commit() { asm volatile("cp.async.commit_group;\n"); }
__device__ __forceinline__ void cp_wait0() { asm volatile("cp.async.wait_group 0;\n"); }
__device__ __forceinline__ void cp_wait1() { asm volatile("cp.async.wait_group 1;\n"); }

__device__ __forceinline__ uint32_t smem_u32(const void* p) {
    return (uint32_t)__cvta_generic_to_shared(p);
}
__device__ __forceinline__ void ldsm_x4(uint32_t* r, uint32_t addr) {
    asm volatile("ldmatrix.sync.aligned.m8n8.x4.shared.b16 {%0,%1,%2,%3}, [%4];"
                 : "=r"(r[0]), "=r"(r[1]), "=r"(r[2]), "=r"(r[3]) : "r"(addr));
}
__device__ __forceinline__ void ldsm_x4_t(uint32_t* r, uint32_t addr) {
    asm volatile("ldmatrix.sync.aligned.m8n8.x4.trans.shared.b16 {%0,%1,%2,%3}, [%4];"
                 : "=r"(r[0]), "=r"(r[1]), "=r"(r[2]), "=r"(r[3]) : "r"(addr));
}
__device__ __forceinline__ void mma_f16(float* d, const uint32_t* a, const uint32_t* b) {
    asm volatile(
        "mma.sync.aligned.m16n8k16.row.col.f32.f16.f16.f32 "
        "{%0,%1,%2,%3}, {%4,%5,%6,%7}, {%8,%9}, {%0,%1,%2,%3};\n"
        : "+f"(d[0]), "+f"(d[1]), "+f"(d[2]), "+f"(d[3])
        : "r"(a[0]), "r"(a[1]), "r"(a[2]), "r"(a[3]), "r"(b[0]), "r"(b[1]));
}

__device__ __forceinline__ float2 block_reduce_sum2(float sum, float sq) {
    __shared__ float sh[16];
    int lane = threadIdx.x & 31, w = threadIdx.x >> 5;
#pragma unroll
    for (int o = 16; o > 0; o >>= 1) {
        sum += __shfl_xor_sync(0xffffffffu, sum, o);
        sq  += __shfl_xor_sync(0xffffffffu, sq, o);
    }
    if (lane == 0) { sh[w] = sum; sh[8 + w] = sq; }
    __syncthreads();
    float s = 0.f, q = 0.f;
#pragma unroll
    for (int i = 0; i < 8; i++) { s += sh[i]; q += sh[8 + i]; }
    return make_float2(s, q);
}

// ---------------- 1) input LayerNorm (fp16 out) ----------------
__global__ __launch_bounds__(256) void ln_in_kernel(const float* __restrict__ x,
                                                    const float* __restrict__ g,
                                                    const float* __restrict__ be) {
    const int row = blockIdx.x, t = threadIdx.x;
    const float* xr = x + (size_t)row * EE;
    const float2 v = *(const float2*)&xr[2 * t];
    float2 r = block_reduce_sum2(v.x + v.y, v.x * v.x + v.y * v.y);
    float mu = r.x * (1.f / 512.f);
    float var = r.y * (1.f / 512.f) - mu * mu;
    float rs = rsqrtf(var + 1e-6f);
    const float2 gg = *(const float2*)&g[2 * t];
    const float2 bb = *(const float2*)&be[2 * t];
    float y0 = (v.x - mu) * rs * gg.x + bb.x;
    float y1 = (v.y - mu) * rs * gg.y + bb.y;
    ((__half2*)(g_normed + (size_t)row * EE))[t] = __floats2half2_rn(y0, y1);
}

// ---------------- 1b) transpose W [E,FF] -> g_Wt [FF,E] fp16 ----------------
__global__ __launch_bounds__(256) void transpose_w_kernel(const float* __restrict__ W) {
    __shared__ float tile[32][33];
    const int tx = threadIdx.x, ty = threadIdx.y;   // 32 x 8
    const int n0 = blockIdx.x * 32, k0 = blockIdx.y * 32;
#pragma unroll
    for (int j = 0; j < 4; j++)
        tile[ty + j * 8][tx] = W[(size_t)(k0 + ty + j * 8) * FF + n0 + tx];
    __syncthreads();
#pragma unroll
    for (int j = 0; j < 4; j++)
        g_Wt[(size_t)(n0 + ty + j * 8) * EE + k0 + tx] = __float2half(tile[tx][ty + j * 8]);
}

// ---------------- 2) projection GEMM (fp16 mma m16n8k16 + ldmatrix) ----------------
// 128x128 tile, BK=64, 256 threads = 8 warps (2m x 4n), warp tile 64x32
#define PROJ_SMEM (4 * 128 * 72 * 2)   // 73728 B
__global__ __launch_bounds__(256) void gemm_proj_kernel() {
    extern __shared__ __half sh[];
    const int t = threadIdx.x;
    const int wid = t >> 5, lane = t & 31;
    const int gid = lane >> 2, tig = lane & 3;
    const int warp_m = wid & 1, warp_n = wid >> 1;
    const int m0 = warp_m * 64, n0 = warp_n * 32;
    const int bm = blockIdx.y * 128, bn = blockIdx.x * 128;

    float acc[4][4][4] = {};

#define PJ_LOAD(st, k0) do {                                                           \
        __half* sA = sh + (st) * 9216;                                                 \
        __half* sB = sh + 18432 + (st) * 9216;                                         \
        _Pragma("unroll")                                                              \
        for (int i = 0; i < 4; i++) {                                                  \
            const int gidx = t + i * 256;                                              \
            const int row = gidx >> 3, q = gidx & 7;                                   \
            cpa16(sA + row * 72 + q * 8, &g_normed[(size_t)(bm + row) * EE + (k0) + q * 8]); \
            cpa16(sB + row * 72 + q * 8, &g_Wt[(size_t)(bn + row) * EE + (k0) + q * 8]);    \
        }                                                                              \
    } while (0)

    PJ_LOAD(0, 0); cp_commit();

    for (int it = 0; it < 8; ++it) {
        if (it < 7) { PJ_LOAD((it + 1) & 1, (it + 1) * 64); cp_commit(); cp_wait1(); }
        else cp_wait0();
        __syncthreads();
        const int st = it & 1;
        const uint32_t aBase = smem_u32(sh + st * 9216);
        const uint32_t bBase = smem_u32(sh + 18432 + st * 9216);
#pragma unroll
        for (int ks = 0; ks < 4; ks++) {
            const int k0h = ks * 16;
            uint32_t af[4][4], bf[2][4];
#pragma unroll
            for (int mi = 0; mi < 4; mi++)
                ldsm_x4(af[mi], aBase + (uint32_t)((m0 + mi * 16 + (lane & 15)) * 144
                                                   + (k0h + ((lane >> 4) << 3)) * 2));
#pragma unroll
            for (int p = 0; p < 2; p++) {
                const int row = n0 + p * 16 + (lane & 7) + ((lane >> 4) << 3);
                const int kadd = ((lane >> 3) & 1) << 3;
                ldsm_x4(bf[p], bBase + (uint32_t)(row * 144 + (k0h + kadd) * 2));
            }
#pragma unroll
            for (int mi = 0; mi < 4; mi++)
#pragma unroll
                for (int ni = 0; ni < 4; ni++)
                    mma_f16(acc[mi][ni], af[mi], &bf[ni >> 1][(ni & 1) * 2]);
        }
        __syncthreads();
    }

    // epilogue: U columns (bn<512) -> fp32 g_u; V/Q/K -> fp16 g_qkv
#pragma unroll
    for (int mi = 0; mi < 4; mi++)
#pragma unroll
        for (int ni = 0; ni < 4; ni++) {
            const int r = bm + m0 + mi * 16 + gid;
            const int c = n0 + ni * 8 + 2 * tig;
            if (bn < 512) {
                *(float2*)&g_u[(size_t)r * LH + bn + c]       = make_float2(acc[mi][ni][0], acc[mi][ni][1]);
                *(float2*)&g_u[(size_t)(r + 8) * LH + bn + c] = make_float2(acc[mi][ni][2], acc[mi][ni][3]);
            } else {
                const int qc = bn - 512 + c;
                *(__half2*)&g_qkv[(size_t)r * QKV_W + qc]       = __floats2half2_rn(acc[mi][ni][0], acc[mi][ni][1]);
                *(__half2*)&g_qkv[(size_t)(r + 8) * QKV_W + qc] = __floats2half2_rn(acc[mi][ni][2], acc[mi][ni][3]);
            }
        }
}

// ---------------- 3) causal silu-attention: 32 q-rows/warp, register P, f16x2 silu ----------------
// grid (32 bh, 16 q-tiles), 128 threads = 4 warps; warp owns 32 q-rows x 64-key tiles (32-key subtiles).
// smem (halves): qs [128][72] @0; 3-stage KV ring @9216: stage st: K @9216+st*9216, V +4608.
#define ATTN_SMEM ((9216 + 3 * 9216) * 2)   // 73728 B
__global__ __launch_bounds__(128, 3) void attn_kernel() {
    extern __shared__ __half sh[];
    __half* qs = sh;

    const int t = threadIdx.x;
    const int wid = t >> 5, lane = t & 31;
    const int gid = lane >> 2, tig = lane & 3;

    const int nt = 15 - blockIdx.y;     // largest workloads in wave 1
    const int bh = blockIdx.x;
    const int b = bh >> 3, h = bh & 7;
    const int nbase = nt << 7;
    const size_t base = (size_t)b * SS;
    const int hd = h << 6;

    const int qrow = wid * 32;                  // warp's local Q-row base (32 rows)
    const int rowmin = nbase + qrow;            // warp's min global q-row

    const int lrow = t >> 3, lq = t & 7;        // loaders (128 threads)

    // Q tile (128 rows) — same commit group as stage 0
#pragma unroll
    for (int i = 0; i < 8; i++) {
        const int row = lrow + i * 16;
        cpa16(qs + row * 72 + lq * 8,
              &g_qkv[(base + nbase + row) * QKV_W + QO_Q + hd + lq * 8]);
    }

#define LOAD_KV_ST(st, m0b) do {                                                        \
        __half* sk = sh + 9216 + (st) * 9216;                                           \
        __half* sv = sk + 4608;                                                         \
        _Pragma("unroll")                                                               \
        for (int i = 0; i < 4; i++) {                                                   \
            const int row = lrow + i * 16;                                              \
            const __half* rowp = &g_qkv[(base + (m0b) + row) * QKV_W + hd + lq * 8];    \
            cpa16(sk + row * 72 + lq * 8, rowp + QO_K);                                 \
            cpa16(sv + row * 72 + lq * 8, rowp + QO_V);                                 \
        }                                                                               \
    } while (0)

    const int nkt = 2 * nt + 2;
    LOAD_KV_ST(0, 0); cp_commit();
    LOAD_KV_ST(1, (nkt > 1 ? 1 : 0) << 6); cp_commit();

    uint32_t aq[2][4][4];       // Q fragments (2 row-groups x 4 d-chunks), loop-resident
    float o[2][8][4] = {};

    for (int kt = 0; kt < nkt; ++kt) {
        cp_wait1();
        __syncthreads();
        // prefetch kt+2 into stage (kt+2)%3 (clamped; != kt%3)
        {
            const int it2 = (kt + 2 < nkt) ? kt + 2 : nkt - 1;
            LOAD_KV_ST((kt + 2) % 3, it2 << 6);
            cp_commit();
        }
        if (kt == 0) {
#pragma unroll
            for (int g = 0; g < 2; g++)
#pragma unroll
                for (int ks = 0; ks < 4; ks++)
                    ldsm_x4(aq[g][ks], smem_u32(qs) +
                            (uint32_t)((qrow + g * 16 + (lane & 15)) * 144
                                       + (ks * 16 + ((lane >> 4) << 3)) * 2));
        }
        const int st = kt % 3;
        const uint32_t kBase = smem_u32(sh + 9216 + st * 9216);
        const uint32_t vBase = kBase + 9216;    // +4608 halves
        const int m0b = kt << 6;

#pragma unroll
        for (int sub = 0; sub < 2; sub++) {
            const int s32 = m0b + sub * 32;
            if (s32 > rowmin + 31) continue;            // subtile fully masked (warp-uniform)

            // ---- S = Q(32x64) @ K^T(64x32) ----
            float s[2][4][4] = {};
#pragma unroll
            for (int ks = 0; ks < 4; ks++) {
                const int d0h = ks * 16;
                uint32_t bk[2][4];
#pragma unroll
                for (int p = 0; p < 2; p++) {
                    const int row = sub * 32 + p * 16 + (lane & 7) + ((lane >> 4) << 3);
                    const int kadd = ((lane >> 3) & 1) << 3;
                    ldsm_x4(bk[p], kBase + (uint32_t)(row * 144 + (d0h + kadd) * 2));
                }
#pragma unroll
                for (int g = 0; g < 2; g++)
#pragma unroll
                    for (int nb = 0; nb < 4; nb++)
                        mma_f16(s[g][nb], aq[g][ks], &bk[nb >> 1][(nb & 1) * 2]);
            }

            // ---- causal mask (only on partial subtiles; warp-uniform branch) ----
            if (s32 + 31 > rowmin) {
#pragma unroll
                for (int g = 0; g < 2; g++)
#pragma unroll
                    for (int nb = 0; nb < 4; nb++) {
                        const int mmb = s32 + nb * 8 + 2 * tig;
#pragma unroll
                        for (int cc = 0; cc < 4; cc++) {
                            const int rr = rowmin + g * 16 + gid + ((cc >> 1) << 3);
                            const int mm = mmb + (cc & 1);
                            if (mm > rr) s[g][nb][cc] = 0.0f;
                        }
                    }
            }

            // ---- silu (f16x2) -> fp16 A-fragments (registers only) ----
            uint32_t pf[2][2][4];
#pragma unroll
            for (int g = 0; g < 2; g++)
#pragma unroll
                for (int kb = 0; kb < 2; kb++) {
                    pf[g][kb][0] = silu2(h2u(__floats2half2_rn(s[g][2*kb][0],   s[g][2*kb][1])));
                    pf[g][kb][1] = silu2(h2u(__floats2half2_rn(s[g][2*kb][2],   s[g][2*kb][3])));
                    pf[g][kb][2] = silu2(h2u(__floats2half2_rn(s[g][2*kb+1][0], s[g][2*kb+1][1])));
                    pf[g][kb][3] = silu2(h2u(__floats2half2_rn(s[g][2*kb+1][2], s[g][2*kb+1][3])));
                }

            // ---- O += P(32x32) @ V(32x64) ----
#pragma unroll
            for (int kb = 0; kb < 2; kb++) {
                const int mk = sub * 32 + kb * 16;
                uint32_t bv[4][4];
#pragma unroll
                for (int db = 0; db < 4; db++) {
                    const int row = mk + (lane & 7) + (((lane >> 3) & 1) << 3);
                    const int col = db * 16 + ((lane >> 4) << 3);
                    ldsm_x4_t(bv[db], vBase + (uint32_t)(row * 144 + col * 2));
                }
#pragma unroll
                for (int g = 0; g < 2; g++)
#pragma unroll
                    for (int dnb = 0; dnb < 8; dnb++)
                        mma_f16(o[g][dnb], pf[g][kb], &bv[dnb >> 1][(dnb & 1) * 2]);
            }
        }
    }

    // ---- write O ----
#pragma unroll
    for (int g = 0; g < 2; g++)
#pragma unroll
        for (int dnb = 0; dnb < 8; dnb++) {
            const size_t r = base + rowmin + g * 16 + gid;
            const int c = hd + dnb * 8 + 2 * tig;
            *(float2*)&g_attn[r * LH + c]       = make_float2(o[g][dnb][0], o[g][dnb][1]);
            *(float2*)&g_attn[(r + 8) * LH + c] = make_float2(o[g][dnb][2], o[g][dnb][3]);
        }
}

// ---------------- 4) output LN * u + residual ----------------
__global__ __launch_bounds__(256) void out_kernel(const float* __restrict__ ue,
                                                  const float* __restrict__ g,
                                                  const float* __restrict__ be,
                                                  float* __restrict__ out) {
    const int row = blockIdx.x, t = threadIdx.x;
    const float* ar = g_attn + (size_t)row * LH;
    float a0 = ar[t], a1 = ar[t + 256];
    float2 r = block_reduce_sum2(a0 + a1, a0 * a0 + a1 * a1);
    float mu = r.x * (1.f / 512.f);
    float var = r.y * (1.f / 512.f) - mu * mu;
    float rs = rsqrtf(var + 1e-6f);
    const float* ur  = g_u + (size_t)row * LH;
    const float* uer = ue + (size_t)row * EE;
    float* orow = out + (size_t)row * EE;
    orow[t]       = uer[t]       + ((a0 - mu) * rs * g[t]       + be[t])       * ur[t];
    orow[t + 256] = uer[t + 256] + ((a1 - mu) * rs * g[t + 256] + be[t + 256]) * ur[t + 256];
}

extern "C" void kernel_launch(void* const* d_in, const int* in_sizes, int n_in,
                              void* d_out, int out_size) {
    (void)in_sizes; (void)n_in; (void)out_size;
    const float* ue   = (const float*)d_in[0];
    const float* uvqk = (const float*)d_in[2];
    const float* ing  = (const float*)d_in[3];
    const float* inb  = (const float*)d_in[4];
    const float* outg = (const float*)d_in[5];
    const float* outb = (const float*)d_in[6];
    float* out = (float*)d_out;

    cudaFuncSetAttribute(gemm_proj_kernel, cudaFuncAttributeMaxDynamicSharedMemorySize, PROJ_SMEM);
    cudaFuncSetAttribute(attn_kernel, cudaFuncAttributeMaxDynamicSharedMemorySize, ATTN_SMEM);

    ln_in_kernel<<<NROW, 256>>>(ue, ing, inb);
    transpose_w_kernel<<<dim3(FF / 32, EE / 32), dim3(32, 8)>>>(uvqk);
    gemm_proj_kernel<<<dim3(FF / 128, NROW / 128), 256, PROJ_SMEM>>>();
    attn_kernel<<<dim3(BB * HH, SS / 128), 128, ATTN_SMEM>>>();
    out_kernel<<<NROW, 256>>>(ue, outg, outb, out);
}

// round 11
// speedup vs baseline: 2.8521x; 1.0031x over previous
#include <cuda_runtime.h>
#include <cuda_fp16.h>
#include <math.h>
#include <stdint.h>

#define EE 512
#define HH 8
#define BB 4
#define SS 2048
#define NROW (BB*SS)            // 8192
#define FF 2048                 // 2LH + 2AH
#define LH 512

// qkv packed layout per row: V @0, Q @512, K @1024 (halves)
#define QKV_W 1536
#define QO_V 0
#define QO_Q 512
#define QO_K 1024

// Scratch (allocation-free rule: __device__ globals)
__device__ __half g_normed[(size_t)NROW*EE];   // 8.4 MB
__device__ __half g_Wt[(size_t)FF*EE];         // 2 MB (W transposed, fp16)
__device__ __half g_qkv[(size_t)NROW*QKV_W];   // 25 MB (V,Q,K fp16)
__device__ float  g_u[(size_t)NROW*LH];        // 16.8 MB (U fp32)
__device__ float  g_attn[(size_t)NROW*LH];     // 16.8 MB

// ---------------- helpers ----------------
__device__ __forceinline__ uint32_t h2u(__half2 h) {
    uint32_t u;
    memcpy(&u, &h, 4);
    return u;
}
// silu on packed half2: y = 0.5x + 0.5x*tanh(0.5x)  (exact tails via tanh saturation)
__device__ __forceinline__ uint32_t silu2(uint32_t x2) {
    __half2 x;
    memcpy(&x, &x2, 4);
    __half2 hx = __hmul2(x, __half2half2(__float2half(0.5f)));
    uint32_t hxu = h2u(hx), thu;
    asm("tanh.approx.f16x2 %0, %1;" : "=r"(thu) : "r"(hxu));
    __half2 th;
    memcpy(&th, &thu, 4);
    __half2 y = __hfma2(hx, th, hx);
    return h2u(y);
}
__device__ __forceinline__ void cpa16(void* dst, const void* src) {
    unsigned u = (unsigned)__cvta_generic_to_shared(dst);
    asm volatile("cp.async.cg.shared.global [%0], [%1], 16;\n" :: "r"(u), "l"(src));
}
__device__ __forceinline__ void cp_commit() { asm volatile("cp.async.commit_group;\n"); }
__device__ __forceinline__ void cp_wait0() { asm volatile("cp.async.wait_group 0;\n"); }
__device__ __forceinline__ void cp_wait1() { asm volatile("cp.async.wait_group 1;\n"); }

__device__ __forceinline__ uint32_t smem_u32(const void* p) {
    return (uint32_t)__cvta_generic_to_shared(p);
}
__device__ __forceinline__ void ldsm_x4(uint32_t* r, uint32_t addr) {
    asm volatile("ldmatrix.sync.aligned.m8n8.x4.shared.b16 {%0,%1,%2,%3}, [%4];"
                 : "=r"(r[0]), "=r"(r[1]), "=r"(r[2]), "=r"(r[3]) : "r"(addr));
}
__device__ __forceinline__ void ldsm_x4_t(uint32_t* r, uint32_t addr) {
    asm volatile("ldmatrix.sync.aligned.m8n8.x4.trans.shared.b16 {%0,%1,%2,%3}, [%4];"
                 : "=r"(r[0]), "=r"(r[1]), "=r"(r[2]), "=r"(r[3]) : "r"(addr));
}
__device__ __forceinline__ void mma_f16(float* d, const uint32_t* a, const uint32_t* b) {
    asm volatile(
        "mma.sync.aligned.m16n8k16.row.col.f32.f16.f16.f32 "
        "{%0,%1,%2,%3}, {%4,%5,%6,%7}, {%8,%9}, {%0,%1,%2,%3};\n"
        : "+f"(d[0]), "+f"(d[1]), "+f"(d[2]), "+f"(d[3])
        : "r"(a[0]), "r"(a[1]), "r"(a[2]), "r"(a[3]), "r"(b[0]), "r"(b[1]));
}

__device__ __forceinline__ float2 block_reduce_sum2(float sum, float sq) {
    __shared__ float sh[16];
    int lane = threadIdx.x & 31, w = threadIdx.x >> 5;
#pragma unroll
    for (int o = 16; o > 0; o >>= 1) {
        sum += __shfl_xor_sync(0xffffffffu, sum, o);
        sq  += __shfl_xor_sync(0xffffffffu, sq, o);
    }
    if (lane == 0) { sh[w] = sum; sh[8 + w] = sq; }
    __syncthreads();
    float s = 0.f, q = 0.f;
#pragma unroll
    for (int i = 0; i < 8; i++) { s += sh[i]; q += sh[8 + i]; }
    return make_float2(s, q);
}

// ---------------- 1) input LayerNorm (fp16 out) ----------------
__global__ __launch_bounds__(256) void ln_in_kernel(const float* __restrict__ x,
                                                    const float* __restrict__ g,
                                                    const float* __restrict__ be) {
    const int row = blockIdx.x, t = threadIdx.x;
    const float* xr = x + (size_t)row * EE;
    const float2 v = *(const float2*)&xr[2 * t];
    float2 r = block_reduce_sum2(v.x + v.y, v.x * v.x + v.y * v.y);
    float mu = r.x * (1.f / 512.f);
    float var = r.y * (1.f / 512.f) - mu * mu;
    float rs = rsqrtf(var + 1e-6f);
    const float2 gg = *(const float2*)&g[2 * t];
    const float2 bb = *(const float2*)&be[2 * t];
    float y0 = (v.x - mu) * rs * gg.x + bb.x;
    float y1 = (v.y - mu) * rs * gg.y + bb.y;
    ((__half2*)(g_normed + (size_t)row * EE))[t] = __floats2half2_rn(y0, y1);
}

// ---------------- 1b) transpose W [E,FF] -> g_Wt [FF,E] fp16 ----------------
__global__ __launch_bounds__(256) void transpose_w_kernel(const float* __restrict__ W) {
    __shared__ float tile[32][33];
    const int tx = threadIdx.x, ty = threadIdx.y;   // 32 x 8
    const int n0 = blockIdx.x * 32, k0 = blockIdx.y * 32;
#pragma unroll
    for (int j = 0; j < 4; j++)
        tile[ty + j * 8][tx] = W[(size_t)(k0 + ty + j * 8) * FF + n0 + tx];
    __syncthreads();
#pragma unroll
    for (int j = 0; j < 4; j++)
        g_Wt[(size_t)(n0 + ty + j * 8) * EE + k0 + tx] = __float2half(tile[tx][ty + j * 8]);
}

// ---------------- 2) projection GEMM (fp16 mma m16n8k16 + ldmatrix) ----------------
// 128x128 tile, BK=64, 256 threads = 8 warps (2m x 4n), warp tile 64x32
#define PROJ_SMEM (4 * 128 * 72 * 2)   // 73728 B
__global__ __launch_bounds__(256) void gemm_proj_kernel() {
    extern __shared__ __half sh[];
    const int t = threadIdx.x;
    const int wid = t >> 5, lane = t & 31;
    const int gid = lane >> 2, tig = lane & 3;
    const int warp_m = wid & 1, warp_n = wid >> 1;
    const int m0 = warp_m * 64, n0 = warp_n * 32;
    const int bm = blockIdx.y * 128, bn = blockIdx.x * 128;

    float acc[4][4][4] = {};

#define PJ_LOAD(st, k0) do {                                                           \
        __half* sA = sh + (st) * 9216;                                                 \
        __half* sB = sh + 18432 + (st) * 9216;                                         \
        _Pragma("unroll")                                                              \
        for (int i = 0; i < 4; i++) {                                                  \
            const int gidx = t + i * 256;                                              \
            const int row = gidx >> 3, q = gidx & 7;                                   \
            cpa16(sA + row * 72 + q * 8, &g_normed[(size_t)(bm + row) * EE + (k0) + q * 8]); \
            cpa16(sB + row * 72 + q * 8, &g_Wt[(size_t)(bn + row) * EE + (k0) + q * 8]);    \
        }                                                                              \
    } while (0)

    PJ_LOAD(0, 0); cp_commit();

    for (int it = 0; it < 8; ++it) {
        if (it < 7) { PJ_LOAD((it + 1) & 1, (it + 1) * 64); cp_commit(); cp_wait1(); }
        else cp_wait0();
        __syncthreads();
        const int st = it & 1;
        const uint32_t aBase = smem_u32(sh + st * 9216);
        const uint32_t bBase = smem_u32(sh + 18432 + st * 9216);
#pragma unroll
        for (int ks = 0; ks < 4; ks++) {
            const int k0h = ks * 16;
            uint32_t af[4][4], bf[2][4];
#pragma unroll
            for (int mi = 0; mi < 4; mi++)
                ldsm_x4(af[mi], aBase + (uint32_t)((m0 + mi * 16 + (lane & 15)) * 144
                                                   + (k0h + ((lane >> 4) << 3)) * 2));
#pragma unroll
            for (int p = 0; p < 2; p++) {
                const int row = n0 + p * 16 + (lane & 7) + ((lane >> 4) << 3);
                const int kadd = ((lane >> 3) & 1) << 3;
                ldsm_x4(bf[p], bBase + (uint32_t)(row * 144 + (k0h + kadd) * 2));
            }
#pragma unroll
            for (int mi = 0; mi < 4; mi++)
#pragma unroll
                for (int ni = 0; ni < 4; ni++)
                    mma_f16(acc[mi][ni], af[mi], &bf[ni >> 1][(ni & 1) * 2]);
        }
        __syncthreads();
    }

    // epilogue: U columns (bn<512) -> fp32 g_u; V/Q/K -> fp16 g_qkv
#pragma unroll
    for (int mi = 0; mi < 4; mi++)
#pragma unroll
        for (int ni = 0; ni < 4; ni++) {
            const int r = bm + m0 + mi * 16 + gid;
            const int c = n0 + ni * 8 + 2 * tig;
            if (bn < 512) {
                *(float2*)&g_u[(size_t)r * LH + bn + c]       = make_float2(acc[mi][ni][0], acc[mi][ni][1]);
                *(float2*)&g_u[(size_t)(r + 8) * LH + bn + c] = make_float2(acc[mi][ni][2], acc[mi][ni][3]);
            } else {
                const int qc = bn - 512 + c;
                *(__half2*)&g_qkv[(size_t)r * QKV_W + qc]       = __floats2half2_rn(acc[mi][ni][0], acc[mi][ni][1]);
                *(__half2*)&g_qkv[(size_t)(r + 8) * QKV_W + qc] = __floats2half2_rn(acc[mi][ni][2], acc[mi][ni][3]);
            }
        }
}

// ---------------- 3) causal silu-attention: paired key tiles, 4-stage ring, desynced warps ----------------
// grid (32 bh, 16 q-tiles), 128 threads = 4 warps; warp owns 32 q-rows x 64-key tiles (32-key subtiles).
// smem (halves): 4-stage KV ring, stage s @ s*9216: K [64][72] @0, V @4608.
// Q staged in stage 3 (dead after fragment extraction at pair 0, then reused by the ring).
#define ATTN_SMEM (4 * 9216 * 2)   // 73728 B
__global__ __launch_bounds__(128, 3) void attn_kernel() {
    extern __shared__ __half sh[];

    const int t = threadIdx.x;
    const int wid = t >> 5, lane = t & 31;
    const int gid = lane >> 2, tig = lane & 3;

    const int nt = 15 - blockIdx.y;     // largest workloads in wave 1
    const int bh = blockIdx.x;
    const int b = bh >> 3, h = bh & 7;
    const int nbase = nt << 7;
    const size_t base = (size_t)b * SS;
    const int hd = h << 6;

    const int qrow = wid * 32;                  // warp's local Q-row base (32 rows)
    const int rowmin = nbase + qrow;            // warp's min global q-row

    const int lrow = t >> 3, lq = t & 7;        // loaders (128 threads)

#define LOAD_KV_ST(st, m0b) do {                                                        \
        __half* sk = sh + (st) * 9216;                                                  \
        __half* sv = sk + 4608;                                                         \
        _Pragma("unroll")                                                               \
        for (int i = 0; i < 4; i++) {                                                   \
            const int row = lrow + i * 16;                                              \
            const __half* rowp = &g_qkv[(base + (m0b) + row) * QKV_W + hd + lq * 8];    \
            cpa16(sk + row * 72 + lq * 8, rowp + QO_K);                                 \
            cpa16(sv + row * 72 + lq * 8, rowp + QO_V);                                 \
        }                                                                               \
    } while (0)

    const int nkt = 2 * nt + 2;                 // always even, >= 2

    // Preload: Q -> stage 3 region (G0 with t0), t1 (G1), t2 clamped (G2)
    {
        __half* qd = sh + 3 * 9216;
#pragma unroll
        for (int i = 0; i < 8; i++) {
            const int row = lrow + i * 16;
            cpa16(qd + row * 72 + lq * 8,
                  &g_qkv[(base + nbase + row) * QKV_W + QO_Q + hd + lq * 8]);
        }
    }
    LOAD_KV_ST(0, 0); cp_commit();
    LOAD_KV_ST(1, 64); cp_commit();
    { const int t2i = (2 < nkt) ? 2 : nkt - 1; LOAD_KV_ST(2, t2i << 6); cp_commit(); }

    uint32_t aq[2][4][4];       // Q fragments, loop-resident
    float o[2][8][4] = {};

    const int npair = nkt >> 1;
    for (int p = 0; p < npair; ++p) {
        cp_wait0();
        __syncthreads();
        if (p == 0) {
            const uint32_t qBase = smem_u32(sh + 3 * 9216);
#pragma unroll
            for (int g = 0; g < 2; g++)
#pragma unroll
                for (int ks = 0; ks < 4; ks++)
                    ldsm_x4(aq[g][ks], qBase +
                            (uint32_t)((qrow + g * 16 + (lane & 15)) * 144
                                       + (ks * 16 + ((lane >> 4) << 3)) * 2));
            __syncthreads();    // fence Q reads before stage-3 prefetch below
        }
        // prefetch tiles 2p+2, 2p+3 into stages consumed last pair (safe post-sync)
        if (2 * p + 2 < nkt) { LOAD_KV_ST((2 * p + 2) & 3, (2 * p + 2) << 6); cp_commit(); }
        if (2 * p + 3 < nkt) { LOAD_KV_ST((2 * p + 3) & 3, (2 * p + 3) << 6); cp_commit(); }

        // process kt = 2p, 2p+1 back-to-back, no intervening sync (warps free-run)
#pragma unroll
        for (int hf = 0; hf < 2; hf++) {
            const int kt = 2 * p + hf;
            const uint32_t kBase = smem_u32(sh + (kt & 3) * 9216);
            const uint32_t vBase = kBase + 9216;    // +4608 halves
            const int m0b = kt << 6;

#pragma unroll
            for (int sub = 0; sub < 2; sub++) {
                const int s32 = m0b + sub * 32;
                if (s32 > rowmin + 31) continue;        // subtile fully masked (warp-uniform)

                // ---- S = Q(32x64) @ K^T(64x32) ----
                float s[2][4][4] = {};
#pragma unroll
                for (int ks = 0; ks < 4; ks++) {
                    const int d0h = ks * 16;
                    uint32_t bk[2][4];
#pragma unroll
                    for (int pp = 0; pp < 2; pp++) {
                        const int row = sub * 32 + pp * 16 + (lane & 7) + ((lane >> 4) << 3);
                        const int kadd = ((lane >> 3) & 1) << 3;
                        ldsm_x4(bk[pp], kBase + (uint32_t)(row * 144 + (d0h + kadd) * 2));
                    }
#pragma unroll
                    for (int g = 0; g < 2; g++)
#pragma unroll
                        for (int nb = 0; nb < 4; nb++)
                            mma_f16(s[g][nb], aq[g][ks], &bk[nb >> 1][(nb & 1) * 2]);
                }

                // ---- causal mask (partial subtiles only; warp-uniform branch) ----
                if (s32 + 31 > rowmin) {
#pragma unroll
                    for (int g = 0; g < 2; g++)
#pragma unroll
                        for (int nb = 0; nb < 4; nb++) {
                            const int mmb = s32 + nb * 8 + 2 * tig;
#pragma unroll
                            for (int cc = 0; cc < 4; cc++) {
                                const int rr = rowmin + g * 16 + gid + ((cc >> 1) << 3);
                                const int mm = mmb + (cc & 1);
                                if (mm > rr) s[g][nb][cc] = 0.0f;
                            }
                        }
                }

                // ---- silu (f16x2) -> fp16 A-fragments (registers only) ----
                uint32_t pf[2][2][4];
#pragma unroll
                for (int g = 0; g < 2; g++)
#pragma unroll
                    for (int kb = 0; kb < 2; kb++) {
                        pf[g][kb][0] = silu2(h2u(__floats2half2_rn(s[g][2*kb][0],   s[g][2*kb][1])));
                        pf[g][kb][1] = silu2(h2u(__floats2half2_rn(s[g][2*kb][2],   s[g][2*kb][3])));
                        pf[g][kb][2] = silu2(h2u(__floats2half2_rn(s[g][2*kb+1][0], s[g][2*kb+1][1])));
                        pf[g][kb][3] = silu2(h2u(__floats2half2_rn(s[g][2*kb+1][2], s[g][2*kb+1][3])));
                    }

                // ---- O += P(32x32) @ V(32x64) ----
#pragma unroll
                for (int kb = 0; kb < 2; kb++) {
                    const int mk = sub * 32 + kb * 16;
                    uint32_t bv[4][4];
#pragma unroll
                    for (int db = 0; db < 4; db++) {
                        const int row = mk + (lane & 7) + (((lane >> 3) & 1) << 3);
                        const int col = db * 16 + ((lane >> 4) << 3);
                        ldsm_x4_t(bv[db], vBase + (uint32_t)(row * 144 + col * 2));
                    }
#pragma unroll
                    for (int g = 0; g < 2; g++)
#pragma unroll
                        for (int dnb = 0; dnb < 8; dnb++)
                            mma_f16(o[g][dnb], pf[g][kb], &bv[dnb >> 1][(dnb & 1) * 2]);
                }
            }
        }
    }

    // ---- write O ----
#pragma unroll
    for (int g = 0; g < 2; g++)
#pragma unroll
        for (int dnb = 0; dnb < 8; dnb++) {
            const size_t r = base + rowmin + g * 16 + gid;
            const int c = hd + dnb * 8 + 2 * tig;
            *(float2*)&g_attn[r * LH + c]       = make_float2(o[g][dnb][0], o[g][dnb][1]);
            *(float2*)&g_attn[(r + 8) * LH + c] = make_float2(o[g][dnb][2], o[g][dnb][3]);
        }
}

// ---------------- 4) output LN * u + residual ----------------
__global__ __launch_bounds__(256) void out_kernel(const float* __restrict__ ue,
                                                  const float* __restrict__ g,
                                                  const float* __restrict__ be,
                                                  float* __restrict__ out) {
    const int row = blockIdx.x, t = threadIdx.x;
    const float* ar = g_attn + (size_t)row * LH;
    float a0 = ar[t], a1 = ar[t + 256];
    float2 r = block_reduce_sum2(a0 + a1, a0 * a0 + a1 * a1);
    float mu = r.x * (1.f / 512.f);
    float var = r.y * (1.f / 512.f) - mu * mu;
    float rs = rsqrtf(var + 1e-6f);
    const float* ur  = g_u + (size_t)row * LH;
    const float* uer = ue + (size_t)row * EE;
    float* orow = out + (size_t)row * EE;
    orow[t]       = uer[t]       + ((a0 - mu) * rs * g[t]       + be[t])       * ur[t];
    orow[t + 256] = uer[t + 256] + ((a1 - mu) * rs * g[t + 256] + be[t + 256]) * ur[t + 256];
}

extern "C" void kernel_launch(void* const* d_in, const int* in_sizes, int n_in,
                              void* d_out, int out_size) {
    (void)in_sizes; (void)n_in; (void)out_size;
    const float* ue   = (const float*)d_in[0];
    const float* uvqk = (const float*)d_in[2];
    const float* ing  = (const float*)d_in[3];
    const float* inb  = (const float*)d_in[4];
    const float* outg = (const float*)d_in[5];
    const float* outb = (const float*)d_in[6];
    float* out = (float*)d_out;

    cudaFuncSetAttribute(gemm_proj_kernel, cudaFuncAttributeMaxDynamicSharedMemorySize, PROJ_SMEM);
    cudaFuncSetAttribute(attn_kernel, cudaFuncAttributeMaxDynamicSharedMemorySize, ATTN_SMEM);

    ln_in_kernel<<<NROW, 256>>>(ue, ing, inb);
    transpose_w_kernel<<<dim3(FF / 32, EE / 32), dim3(32, 8)>>>(uvqk);
    gemm_proj_kernel<<<dim3(FF / 128, NROW / 128), 256, PROJ_SMEM>>>();
    attn_kernel<<<dim3(BB * HH, SS / 128), 128, ATTN_SMEM>>>();
    out_kernel<<<NROW, 256>>>(ue, outg, outb, out);
}

// round 12
// speedup vs baseline: 3.0442x; 1.0674x over previous
#include <cuda_runtime.h>
#include <cuda_fp16.h>
#include <math.h>
#include <stdint.h>

#define EE 512
#define HH 8
#define BB 4
#define SS 2048
#define NROW (BB*SS)            // 8192
#define FF 2048                 // 2LH + 2AH
#define LH 512

// qkv packed layout per row: V @0, Q @512, K @1024 (halves)
#define QKV_W 1536
#define QO_V 0
#define QO_Q 512
#define QO_K 1024

// Scratch (allocation-free rule: __device__ globals)
__device__ __half g_normed[(size_t)NROW*EE];   // 8.4 MB
__device__ __half g_Wt[(size_t)FF*EE];         // 2 MB (W transposed, fp16)
__device__ __half g_qkv[(size_t)NROW*QKV_W];   // 25 MB (V,Q,K fp16)
__device__ float  g_u[(size_t)NROW*LH];        // 16.8 MB (U fp32)
__device__ float  g_attn[(size_t)NROW*LH];     // 16.8 MB

// ---------------- helpers ----------------
__device__ __forceinline__ uint32_t h2u(__half2 h) {
    uint32_t u;
    memcpy(&u, &h, 4);
    return u;
}
__device__ __forceinline__ __half2 u2h(uint32_t u) {
    __half2 h;
    memcpy(&h, &u, 4);
    return h;
}
// silu on packed half2: y = 0.5x + 0.5x*tanh(0.5x)  (exact tails via tanh saturation)
__device__ __forceinline__ uint32_t silu2(uint32_t x2) {
    __half2 x = u2h(x2);
    __half2 hx = __hmul2(x, __half2half2(__float2half(0.5f)));
    uint32_t hxu = h2u(hx), thu;
    asm("tanh.approx.f16x2 %0, %1;" : "=r"(thu) : "r"(hxu));
    __half2 y = __hfma2(hx, u2h(thu), hx);
    return h2u(y);
}
__device__ __forceinline__ void cpa16(void* dst, const void* src) {
    unsigned u = (unsigned)__cvta_generic_to_shared(dst);
    asm volatile("cp.async.cg.shared.global [%0], [%1], 16;\n" :: "r"(u), "l"(src));
}
__device__ __forceinline__ void cp_commit() { asm volatile("cp.async.commit_group;\n"); }
__device__ __forceinline__ void cp_wait0() { asm volatile("cp.async.wait_group 0;\n"); }
__device__ __forceinline__ void cp_wait1() { asm volatile("cp.async.wait_group 1;\n"); }

__device__ __forceinline__ uint32_t smem_u32(const void* p) {
    return (uint32_t)__cvta_generic_to_shared(p);
}
__device__ __forceinline__ void ldsm_x4(uint32_t* r, uint32_t addr) {
    asm volatile("ldmatrix.sync.aligned.m8n8.x4.shared.b16 {%0,%1,%2,%3}, [%4];"
                 : "=r"(r[0]), "=r"(r[1]), "=r"(r[2]), "=r"(r[3]) : "r"(addr));
}
__device__ __forceinline__ void ldsm_x4_t(uint32_t* r, uint32_t addr) {
    asm volatile("ldmatrix.sync.aligned.m8n8.x4.trans.shared.b16 {%0,%1,%2,%3}, [%4];"
                 : "=r"(r[0]), "=r"(r[1]), "=r"(r[2]), "=r"(r[3]) : "r"(addr));
}
__device__ __forceinline__ void mma_f16(float* d, const uint32_t* a, const uint32_t* b) {
    asm volatile(
        "mma.sync.aligned.m16n8k16.row.col.f32.f16.f16.f32 "
        "{%0,%1,%2,%3}, {%4,%5,%6,%7}, {%8,%9}, {%0,%1,%2,%3};\n"
        : "+f"(d[0]), "+f"(d[1]), "+f"(d[2]), "+f"(d[3])
        : "r"(a[0]), "r"(a[1]), "r"(a[2]), "r"(a[3]), "r"(b[0]), "r"(b[1]));
}
// f16 accumulation (double-rate); D-fragment layout == A-fragment layout of next mma
__device__ __forceinline__ void mma_f16acc(uint32_t* d, const uint32_t* a, const uint32_t* b) {
    asm volatile(
        "mma.sync.aligned.m16n8k16.row.col.f16.f16.f16.f16 "
        "{%0,%1}, {%2,%3,%4,%5}, {%6,%7}, {%0,%1};\n"
        : "+r"(d[0]), "+r"(d[1])
        : "r"(a[0]), "r"(a[1]), "r"(a[2]), "r"(a[3]), "r"(b[0]), "r"(b[1]));
}

__device__ __forceinline__ float2 block_reduce_sum2_128(float sum, float sq) {
    __shared__ float sh[8];
    int lane = threadIdx.x & 31, w = threadIdx.x >> 5;
#pragma unroll
    for (int o = 16; o > 0; o >>= 1) {
        sum += __shfl_xor_sync(0xffffffffu, sum, o);
        sq  += __shfl_xor_sync(0xffffffffu, sq, o);
    }
    if (lane == 0) { sh[w] = sum; sh[4 + w] = sq; }
    __syncthreads();
    float s = 0.f, q = 0.f;
#pragma unroll
    for (int i = 0; i < 4; i++) { s += sh[i]; q += sh[4 + i]; }
    return make_float2(s, q);
}

// ---------------- 1) input LayerNorm (fp16 out, float4 loads) ----------------
__global__ __launch_bounds__(128) void ln_in_kernel(const float* __restrict__ x,
                                                    const float* __restrict__ g,
                                                    const float* __restrict__ be) {
    const int row = blockIdx.x, t = threadIdx.x;
    const float4 v = *(const float4*)&x[(size_t)row * EE + 4 * t];
    float2 r = block_reduce_sum2_128(v.x + v.y + v.z + v.w,
                                     v.x * v.x + v.y * v.y + v.z * v.z + v.w * v.w);
    float mu = r.x * (1.f / 512.f);
    float var = r.y * (1.f / 512.f) - mu * mu;
    float rs = rsqrtf(var + 1e-6f);
    const float4 gg = *(const float4*)&g[4 * t];
    const float4 bb = *(const float4*)&be[4 * t];
    __half2 y0 = __floats2half2_rn((v.x - mu) * rs * gg.x + bb.x, (v.y - mu) * rs * gg.y + bb.y);
    __half2 y1 = __floats2half2_rn((v.z - mu) * rs * gg.z + bb.z, (v.w - mu) * rs * gg.w + bb.w);
    __half2* orow = (__half2*)(g_normed + (size_t)row * EE);
    orow[2 * t] = y0; orow[2 * t + 1] = y1;
}

// ---------------- 1b) transpose W [E,FF] -> g_Wt [FF,E] fp16 ----------------
__global__ __launch_bounds__(256) void transpose_w_kernel(const float* __restrict__ W) {
    __shared__ float tile[32][33];
    const int tx = threadIdx.x, ty = threadIdx.y;   // 32 x 8
    const int n0 = blockIdx.x * 32, k0 = blockIdx.y * 32;
#pragma unroll
    for (int j = 0; j < 4; j++)
        tile[ty + j * 8][tx] = W[(size_t)(k0 + ty + j * 8) * FF + n0 + tx];
    __syncthreads();
#pragma unroll
    for (int j = 0; j < 4; j++)
        g_Wt[(size_t)(n0 + ty + j * 8) * EE + k0 + tx] = __float2half(tile[tx][ty + j * 8]);
}

// ---------------- 2) projection GEMM (fp16 mma m16n8k16 + ldmatrix) ----------------
// 128x128 tile, BK=64, 256 threads = 8 warps (2m x 4n), warp tile 64x32
#define PROJ_SMEM (4 * 128 * 72 * 2)   // 73728 B
__global__ __launch_bounds__(256) void gemm_proj_kernel() {
    extern __shared__ __half sh[];
    const int t = threadIdx.x;
    const int wid = t >> 5, lane = t & 31;
    const int gid = lane >> 2, tig = lane & 3;
    const int warp_m = wid & 1, warp_n = wid >> 1;
    const int m0 = warp_m * 64, n0 = warp_n * 32;
    const int bm = blockIdx.y * 128, bn = blockIdx.x * 128;

    float acc[4][4][4] = {};

#define PJ_LOAD(st, k0) do {                                                           \
        __half* sA = sh + (st) * 9216;                                                 \
        __half* sB = sh + 18432 + (st) * 9216;                                         \
        _Pragma("unroll")                                                              \
        for (int i = 0; i < 4; i++) {                                                  \
            const int gidx = t + i * 256;                                              \
            const int row = gidx >> 3, q = gidx & 7;                                   \
            cpa16(sA + row * 72 + q * 8, &g_normed[(size_t)(bm + row) * EE + (k0) + q * 8]); \
            cpa16(sB + row * 72 + q * 8, &g_Wt[(size_t)(bn + row) * EE + (k0) + q * 8]);    \
        }                                                                              \
    } while (0)

    PJ_LOAD(0, 0); cp_commit();

    for (int it = 0; it < 8; ++it) {
        if (it < 7) { PJ_LOAD((it + 1) & 1, (it + 1) * 64); cp_commit(); cp_wait1(); }
        else cp_wait0();
        __syncthreads();
        const int st = it & 1;
        const uint32_t aBase = smem_u32(sh + st * 9216);
        const uint32_t bBase = smem_u32(sh + 18432 + st * 9216);
#pragma unroll
        for (int ks = 0; ks < 4; ks++) {
            const int k0h = ks * 16;
            uint32_t af[4][4], bf[2][4];
#pragma unroll
            for (int mi = 0; mi < 4; mi++)
                ldsm_x4(af[mi], aBase + (uint32_t)((m0 + mi * 16 + (lane & 15)) * 144
                                                   + (k0h + ((lane >> 4) << 3)) * 2));
#pragma unroll
            for (int p = 0; p < 2; p++) {
                const int row = n0 + p * 16 + (lane & 7) + ((lane >> 4) << 3);
                const int kadd = ((lane >> 3) & 1) << 3;
                ldsm_x4(bf[p], bBase + (uint32_t)(row * 144 + (k0h + kadd) * 2));
            }
#pragma unroll
            for (int mi = 0; mi < 4; mi++)
#pragma unroll
                for (int ni = 0; ni < 4; ni++)
                    mma_f16(acc[mi][ni], af[mi], &bf[ni >> 1][(ni & 1) * 2]);
        }
        __syncthreads();
    }

    // epilogue: U columns (bn<512) -> fp32 g_u; V/Q/K -> fp16 g_qkv
#pragma unroll
    for (int mi = 0; mi < 4; mi++)
#pragma unroll
        for (int ni = 0; ni < 4; ni++) {
            const int r = bm + m0 + mi * 16 + gid;
            const int c = n0 + ni * 8 + 2 * tig;
            if (bn < 512) {
                *(float2*)&g_u[(size_t)r * LH + bn + c]       = make_float2(acc[mi][ni][0], acc[mi][ni][1]);
                *(float2*)&g_u[(size_t)(r + 8) * LH + bn + c] = make_float2(acc[mi][ni][2], acc[mi][ni][3]);
            } else {
                const int qc = bn - 512 + c;
                *(__half2*)&g_qkv[(size_t)r * QKV_W + qc]       = __floats2half2_rn(acc[mi][ni][0], acc[mi][ni][1]);
                *(__half2*)&g_qkv[(size_t)(r + 8) * QKV_W + qc] = __floats2half2_rn(acc[mi][ni][2], acc[mi][ni][3]);
            }
        }
}

// ---------------- 3) causal silu-attention: f16-accum S GEMM, register P ----------------
// grid (32 bh, 16 q-tiles), 128 threads = 4 warps; warp owns 32 q-rows x 64-key tiles (32-key subtiles).
// smem (halves): 4-stage KV ring, stage s @ s*9216: K [64][72] @0, V @4608.
// Q staged in stage 3 (dead after fragment extraction at pair 0, then reused by the ring).
#define ATTN_SMEM (4 * 9216 * 2)   // 73728 B
__global__ __launch_bounds__(128, 3) void attn_kernel() {
    extern __shared__ __half sh[];

    const int t = threadIdx.x;
    const int wid = t >> 5, lane = t & 31;
    const int gid = lane >> 2, tig = lane & 3;

    const int nt = 15 - blockIdx.y;     // largest workloads in wave 1
    const int bh = blockIdx.x;
    const int b = bh >> 3, h = bh & 7;
    const int nbase = nt << 7;
    const size_t base = (size_t)b * SS;
    const int hd = h << 6;

    const int qrow = wid * 32;                  // warp's local Q-row base (32 rows)
    const int rowmin = nbase + qrow;            // warp's min global q-row

    const int lrow = t >> 3, lq = t & 7;        // loaders (128 threads)

#define LOAD_KV_ST(st, m0b) do {                                                        \
        __half* sk = sh + (st) * 9216;                                                  \
        __half* sv = sk + 4608;                                                         \
        _Pragma("unroll")                                                               \
        for (int i = 0; i < 4; i++) {                                                   \
            const int row = lrow + i * 16;                                              \
            const __half* rowp = &g_qkv[(base + (m0b) + row) * QKV_W + hd + lq * 8];    \
            cpa16(sk + row * 72 + lq * 8, rowp + QO_K);                                 \
            cpa16(sv + row * 72 + lq * 8, rowp + QO_V);                                 \
        }                                                                               \
    } while (0)

    const int nkt = 2 * nt + 2;                 // always even, >= 2

    // Preload: Q -> stage 3 region, then KV tiles 0,1,2 (clamped)
    {
        __half* qd = sh + 3 * 9216;
#pragma unroll
        for (int i = 0; i < 8; i++) {
            const int row = lrow + i * 16;
            cpa16(qd + row * 72 + lq * 8,
                  &g_qkv[(base + nbase + row) * QKV_W + QO_Q + hd + lq * 8]);
        }
    }
    LOAD_KV_ST(0, 0); cp_commit();
    LOAD_KV_ST(1, 64); cp_commit();
    { const int t2i = (2 < nkt) ? 2 : nkt - 1; LOAD_KV_ST(2, t2i << 6); cp_commit(); }

    uint32_t aq[2][4][4];       // Q fragments, loop-resident
    float o[2][8][4] = {};

    const int npair = nkt >> 1;
    for (int p = 0; p < npair; ++p) {
        cp_wait0();
        __syncthreads();
        if (p == 0) {
            const uint32_t qBase = smem_u32(sh + 3 * 9216);
#pragma unroll
            for (int g = 0; g < 2; g++)
#pragma unroll
                for (int ks = 0; ks < 4; ks++)
                    ldsm_x4(aq[g][ks], qBase +
                            (uint32_t)((qrow + g * 16 + (lane & 15)) * 144
                                       + (ks * 16 + ((lane >> 4) << 3)) * 2));
            __syncthreads();    // fence Q reads before stage-3 prefetch below
        }
        // prefetch tiles 2p+2, 2p+3 into stages consumed last pair (safe post-sync)
        if (2 * p + 2 < nkt) { LOAD_KV_ST((2 * p + 2) & 3, (2 * p + 2) << 6); cp_commit(); }
        if (2 * p + 3 < nkt) { LOAD_KV_ST((2 * p + 3) & 3, (2 * p + 3) << 6); cp_commit(); }

        // process kt = 2p, 2p+1 back-to-back, no intervening sync
#pragma unroll
        for (int hf = 0; hf < 2; hf++) {
            const int kt = 2 * p + hf;
            const uint32_t kBase = smem_u32(sh + (kt & 3) * 9216);
            const uint32_t vBase = kBase + 9216;    // +4608 halves
            const int m0b = kt << 6;

#pragma unroll
            for (int sub = 0; sub < 2; sub++) {
                const int s32 = m0b + sub * 32;
                if (s32 > rowmin + 31) continue;        // subtile fully masked (warp-uniform)

                // ---- S = Q(32x64) @ K^T(64x32), f16 accumulation (double rate) ----
                uint32_t s2[2][4][2] = {};              // packed half2 accumulators
#pragma unroll
                for (int ks = 0; ks < 4; ks++) {
                    const int d0h = ks * 16;
                    uint32_t bk[2][4];
#pragma unroll
                    for (int pp = 0; pp < 2; pp++) {
                        const int row = sub * 32 + pp * 16 + (lane & 7) + ((lane >> 4) << 3);
                        const int kadd = ((lane >> 3) & 1) << 3;
                        ldsm_x4(bk[pp], kBase + (uint32_t)(row * 144 + (d0h + kadd) * 2));
                    }
#pragma unroll
                    for (int g = 0; g < 2; g++)
#pragma unroll
                        for (int nb = 0; nb < 4; nb++)
                            mma_f16acc(s2[g][nb], aq[g][ks], &bk[nb >> 1][(nb & 1) * 2]);
                }

                // ---- causal mask (partial subtiles only; exact-int fp16 compare) ----
                if (s32 + 31 > rowmin) {
#pragma unroll
                    for (int g = 0; g < 2; g++) {
                        const float rbase = (float)(rowmin + g * 16 + gid);
#pragma unroll
                        for (int nb = 0; nb < 4; nb++) {
                            const int mm = s32 + nb * 8 + 2 * tig;
                            const __half2 cols = __floats2half2_rn((float)mm, (float)(mm + 1));
#pragma unroll
                            for (int rg = 0; rg < 2; rg++) {
                                const __half2 rows = __half2half2(__float2half(rbase + rg * 8));
                                const __half2 keep = __hle2(cols, rows);   // col<=row -> 1.0
                                s2[g][nb][rg] = h2u(__hmul2(u2h(s2[g][nb][rg]), keep));
                            }
                        }
                    }
                }

                // ---- silu (f16x2) directly on accumulator regs = A-fragments ----
                uint32_t pf[2][2][4];
#pragma unroll
                for (int g = 0; g < 2; g++)
#pragma unroll
                    for (int kb = 0; kb < 2; kb++) {
                        pf[g][kb][0] = silu2(s2[g][2 * kb][0]);
                        pf[g][kb][1] = silu2(s2[g][2 * kb][1]);
                        pf[g][kb][2] = silu2(s2[g][2 * kb + 1][0]);
                        pf[g][kb][3] = silu2(s2[g][2 * kb + 1][1]);
                    }

                // ---- O += P(32x32) @ V(32x64), fp32 accumulation ----
#pragma unroll
                for (int kb = 0; kb < 2; kb++) {
                    const int mk = sub * 32 + kb * 16;
                    uint32_t bv[4][4];
#pragma unroll
                    for (int db = 0; db < 4; db++) {
                        const int row = mk + (lane & 7) + (((lane >> 3) & 1) << 3);
                        const int col = db * 16 + ((lane >> 4) << 3);
                        ldsm_x4_t(bv[db], vBase + (uint32_t)(row * 144 + col * 2));
                    }
#pragma unroll
                    for (int g = 0; g < 2; g++)
#pragma unroll
                        for (int dnb = 0; dnb < 8; dnb++)
                            mma_f16(o[g][dnb], pf[g][kb], &bv[dnb >> 1][(dnb & 1) * 2]);
                }
            }
        }
    }

    // ---- write O ----
#pragma unroll
    for (int g = 0; g < 2; g++)
#pragma unroll
        for (int dnb = 0; dnb < 8; dnb++) {
            const size_t r = base + rowmin + g * 16 + gid;
            const int c = hd + dnb * 8 + 2 * tig;
            *(float2*)&g_attn[r * LH + c]       = make_float2(o[g][dnb][0], o[g][dnb][1]);
            *(float2*)&g_attn[(r + 8) * LH + c] = make_float2(o[g][dnb][2], o[g][dnb][3]);
        }
}

// ---------------- 4) output LN * u + residual (float4) ----------------
__global__ __launch_bounds__(128) void out_kernel(const float* __restrict__ ue,
                                                  const float* __restrict__ g,
                                                  const float* __restrict__ be,
                                                  float* __restrict__ out) {
    const int row = blockIdx.x, t = threadIdx.x;
    const float4 a = *(const float4*)&g_attn[(size_t)row * LH + 4 * t];
    float2 r = block_reduce_sum2_128(a.x + a.y + a.z + a.w,
                                     a.x * a.x + a.y * a.y + a.z * a.z + a.w * a.w);
    float mu = r.x * (1.f / 512.f);
    float var = r.y * (1.f / 512.f) - mu * mu;
    float rs = rsqrtf(var + 1e-6f);
    const float4 gg = *(const float4*)&g[4 * t];
    const float4 bb = *(const float4*)&be[4 * t];
    const float4 uu = *(const float4*)&g_u[(size_t)row * LH + 4 * t];
    const float4 ee = *(const float4*)&ue[(size_t)row * EE + 4 * t];
    float4 yy;
    yy.x = ee.x + ((a.x - mu) * rs * gg.x + bb.x) * uu.x;
    yy.y = ee.y + ((a.y - mu) * rs * gg.y + bb.y) * uu.y;
    yy.z = ee.z + ((a.z - mu) * rs * gg.z + bb.z) * uu.z;
    yy.w = ee.w + ((a.w - mu) * rs * gg.w + bb.w) * uu.w;
    *(float4*)&out[(size_t)row * EE + 4 * t] = yy;
}

extern "C" void kernel_launch(void* const* d_in, const int* in_sizes, int n_in,
                              void* d_out, int out_size) {
    (void)in_sizes; (void)n_in; (void)out_size;
    const float* ue   = (const float*)d_in[0];
    const float* uvqk = (const float*)d_in[2];
    const float* ing  = (const float*)d_in[3];
    const float* inb  = (const float*)d_in[4];
    const float* outg = (const float*)d_in[5];
    const float* outb = (const float*)d_in[6];
    float* out = (float*)d_out;

    cudaFuncSetAttribute(gemm_proj_kernel, cudaFuncAttributeMaxDynamicSharedMemorySize, PROJ_SMEM);
    cudaFuncSetAttribute(attn_kernel, cudaFuncAttributeMaxDynamicSharedMemorySize, ATTN_SMEM);

    ln_in_kernel<<<NROW, 128>>>(ue, ing, inb);
    transpose_w_kernel<<<dim3(FF / 32, EE / 32), dim3(32, 8)>>>(uvqk);
    gemm_proj_kernel<<<dim3(FF / 128, NROW / 128), 256, PROJ_SMEM>>>();
    attn_kernel<<<dim3(BB * HH, SS / 128), 128, ATTN_SMEM>>>();
    out_kernel<<<NROW, 128>>>(ue, outg, outb, out);
}

// round 13
// speedup vs baseline: 3.1318x; 1.0288x over previous
#include <cuda_runtime.h>
#include <cuda_fp16.h>
#include <math.h>
#include <stdint.h>

#define EE 512
#define HH 8
#define BB 4
#define SS 2048
#define NROW (BB*SS)            // 8192
#define FF 2048                 // 2LH + 2AH
#define LH 512

// qkv packed layout per row: V @0, Q @512, K @1024 (halves)
#define QKV_W 1536
#define QO_V 0
#define QO_Q 512
#define QO_K 1024

// Scratch (allocation-free rule: __device__ globals)
__device__ __half g_normed[(size_t)NROW*EE];   // 8.4 MB
__device__ __half g_Wt[(size_t)FF*EE];         // 2 MB (W transposed, fp16)
__device__ __half g_qkv[(size_t)NROW*QKV_W];   // 25 MB (V,Q,K fp16)
__device__ float  g_u[(size_t)NROW*LH];        // 16.8 MB (U fp32)
__device__ float  g_attn[(size_t)NROW*LH];     // 16.8 MB

// ---------------- helpers ----------------
__device__ __forceinline__ uint32_t h2u(__half2 h) {
    uint32_t u;
    memcpy(&u, &h, 4);
    return u;
}
__device__ __forceinline__ __half2 u2h(uint32_t u) {
    __half2 h;
    memcpy(&h, &u, 4);
    return h;
}
// silu on packed half2: y = 0.5x + 0.5x*tanh(0.5x)  (exact tails via tanh saturation)
__device__ __forceinline__ uint32_t silu2(uint32_t x2) {
    __half2 x = u2h(x2);
    __half2 hx = __hmul2(x, __half2half2(__float2half(0.5f)));
    uint32_t hxu = h2u(hx), thu;
    asm("tanh.approx.f16x2 %0, %1;" : "=r"(thu) : "r"(hxu));
    __half2 y = __hfma2(hx, u2h(thu), hx);
    return h2u(y);
}
__device__ __forceinline__ void cpa16(void* dst, const void* src) {
    unsigned u = (unsigned)__cvta_generic_to_shared(dst);
    asm volatile("cp.async.cg.shared.global [%0], [%1], 16;\n" :: "r"(u), "l"(src));
}
__device__ __forceinline__ void cp_commit() { asm volatile("cp.async.commit_group;\n"); }
__device__ __forceinline__ void cp_wait0() { asm volatile("cp.async.wait_group 0;\n"); }
__device__ __forceinline__ void cp_wait1() { asm volatile("cp.async.wait_group 1;\n"); }

__device__ __forceinline__ uint32_t smem_u32(const void* p) {
    return (uint32_t)__cvta_generic_to_shared(p);
}
__device__ __forceinline__ void ldsm_x4(uint32_t* r, uint32_t addr) {
    asm volatile("ldmatrix.sync.aligned.m8n8.x4.shared.b16 {%0,%1,%2,%3}, [%4];"
                 : "=r"(r[0]), "=r"(r[1]), "=r"(r[2]), "=r"(r[3]) : "r"(addr));
}
__device__ __forceinline__ void ldsm_x4_t(uint32_t* r, uint32_t addr) {
    asm volatile("ldmatrix.sync.aligned.m8n8.x4.trans.shared.b16 {%0,%1,%2,%3}, [%4];"
                 : "=r"(r[0]), "=r"(r[1]), "=r"(r[2]), "=r"(r[3]) : "r"(addr));
}
__device__ __forceinline__ void mma_f16(float* d, const uint32_t* a, const uint32_t* b) {
    asm volatile(
        "mma.sync.aligned.m16n8k16.row.col.f32.f16.f16.f32 "
        "{%0,%1,%2,%3}, {%4,%5,%6,%7}, {%8,%9}, {%0,%1,%2,%3};\n"
        : "+f"(d[0]), "+f"(d[1]), "+f"(d[2]), "+f"(d[3])
        : "r"(a[0]), "r"(a[1]), "r"(a[2]), "r"(a[3]), "r"(b[0]), "r"(b[1]));
}
// f16 accumulation; D-fragment layout == A-fragment layout of next mma
__device__ __forceinline__ void mma_f16acc(uint32_t* d, const uint32_t* a, const uint32_t* b) {
    asm volatile(
        "mma.sync.aligned.m16n8k16.row.col.f16.f16.f16.f16 "
        "{%0,%1}, {%2,%3,%4,%5}, {%6,%7}, {%0,%1};\n"
        : "+r"(d[0]), "+r"(d[1])
        : "r"(a[0]), "r"(a[1]), "r"(a[2]), "r"(a[3]), "r"(b[0]), "r"(b[1]));
}

__device__ __forceinline__ float2 block_reduce_sum2_128(float sum, float sq) {
    __shared__ float sh[8];
    int lane = threadIdx.x & 31, w = threadIdx.x >> 5;
#pragma unroll
    for (int o = 16; o > 0; o >>= 1) {
        sum += __shfl_xor_sync(0xffffffffu, sum, o);
        sq  += __shfl_xor_sync(0xffffffffu, sq, o);
    }
    if (lane == 0) { sh[w] = sum; sh[4 + w] = sq; }
    __syncthreads();
    float s = 0.f, q = 0.f;
#pragma unroll
    for (int i = 0; i < 4; i++) { s += sh[i]; q += sh[4 + i]; }
    return make_float2(s, q);
}

// ---------------- 1) input LayerNorm (fp16 out, float4 loads) ----------------
__global__ __launch_bounds__(128) void ln_in_kernel(const float* __restrict__ x,
                                                    const float* __restrict__ g,
                                                    const float* __restrict__ be) {
    const int row = blockIdx.x, t = threadIdx.x;
    const float4 v = *(const float4*)&x[(size_t)row * EE + 4 * t];
    float2 r = block_reduce_sum2_128(v.x + v.y + v.z + v.w,
                                     v.x * v.x + v.y * v.y + v.z * v.z + v.w * v.w);
    float mu = r.x * (1.f / 512.f);
    float var = r.y * (1.f / 512.f) - mu * mu;
    float rs = rsqrtf(var + 1e-6f);
    const float4 gg = *(const float4*)&g[4 * t];
    const float4 bb = *(const float4*)&be[4 * t];
    __half2 y0 = __floats2half2_rn((v.x - mu) * rs * gg.x + bb.x, (v.y - mu) * rs * gg.y + bb.y);
    __half2 y1 = __floats2half2_rn((v.z - mu) * rs * gg.z + bb.z, (v.w - mu) * rs * gg.w + bb.w);
    __half2* orow = (__half2*)(g_normed + (size_t)row * EE);
    orow[2 * t] = y0; orow[2 * t + 1] = y1;
}

// ---------------- 1b) transpose W [E,FF] -> g_Wt [FF,E] fp16 ----------------
__global__ __launch_bounds__(256) void transpose_w_kernel(const float* __restrict__ W) {
    __shared__ float tile[32][33];
    const int tx = threadIdx.x, ty = threadIdx.y;   // 32 x 8
    const int n0 = blockIdx.x * 32, k0 = blockIdx.y * 32;
#pragma unroll
    for (int j = 0; j < 4; j++)
        tile[ty + j * 8][tx] = W[(size_t)(k0 + ty + j * 8) * FF + n0 + tx];
    __syncthreads();
#pragma unroll
    for (int j = 0; j < 4; j++)
        g_Wt[(size_t)(n0 + ty + j * 8) * EE + k0 + tx] = __float2half(tile[tx][ty + j * 8]);
}

// ---------------- 2) projection GEMM (fp16 mma m16n8k16 + ldmatrix) ----------------
// 128x128 tile, BK=64, 256 threads = 8 warps (2m x 4n), warp tile 64x32.
// Epilogue: QKV tiles staged via smem for 16B-coalesced global stores.
#define PROJ_SMEM (4 * 128 * 72 * 2)   // 73728 B
__global__ __launch_bounds__(256) void gemm_proj_kernel() {
    extern __shared__ __half sh[];
    const int t = threadIdx.x;
    const int wid = t >> 5, lane = t & 31;
    const int gid = lane >> 2, tig = lane & 3;
    const int warp_m = wid & 1, warp_n = wid >> 1;
    const int m0 = warp_m * 64, n0 = warp_n * 32;
    const int bm = blockIdx.y * 128, bn = blockIdx.x * 128;

    float acc[4][4][4] = {};

#define PJ_LOAD(st, k0) do {                                                           \
        __half* sA = sh + (st) * 9216;                                                 \
        __half* sB = sh + 18432 + (st) * 9216;                                         \
        _Pragma("unroll")                                                              \
        for (int i = 0; i < 4; i++) {                                                  \
            const int gidx = t + i * 256;                                              \
            const int row = gidx >> 3, q = gidx & 7;                                   \
            cpa16(sA + row * 72 + q * 8, &g_normed[(size_t)(bm + row) * EE + (k0) + q * 8]); \
            cpa16(sB + row * 72 + q * 8, &g_Wt[(size_t)(bn + row) * EE + (k0) + q * 8]);    \
        }                                                                              \
    } while (0)

    PJ_LOAD(0, 0); cp_commit();

    for (int it = 0; it < 8; ++it) {
        if (it < 7) { PJ_LOAD((it + 1) & 1, (it + 1) * 64); cp_commit(); cp_wait1(); }
        else cp_wait0();
        __syncthreads();
        const int st = it & 1;
        const uint32_t aBase = smem_u32(sh + st * 9216);
        const uint32_t bBase = smem_u32(sh + 18432 + st * 9216);
#pragma unroll
        for (int ks = 0; ks < 4; ks++) {
            const int k0h = ks * 16;
            uint32_t af[4][4], bf[2][4];
#pragma unroll
            for (int mi = 0; mi < 4; mi++)
                ldsm_x4(af[mi], aBase + (uint32_t)((m0 + mi * 16 + (lane & 15)) * 144
                                                   + (k0h + ((lane >> 4) << 3)) * 2));
#pragma unroll
            for (int p = 0; p < 2; p++) {
                const int row = n0 + p * 16 + (lane & 7) + ((lane >> 4) << 3);
                const int kadd = ((lane >> 3) & 1) << 3;
                ldsm_x4(bf[p], bBase + (uint32_t)(row * 144 + (k0h + kadd) * 2));
            }
#pragma unroll
            for (int mi = 0; mi < 4; mi++)
#pragma unroll
                for (int ni = 0; ni < 4; ni++)
                    mma_f16(acc[mi][ni], af[mi], &bf[ni >> 1][(ni & 1) * 2]);
        }
        __syncthreads();
    }

    if (bn < 512) {
        // U columns -> fp32 g_u (direct stores: 32B segments, already coalesced)
#pragma unroll
        for (int mi = 0; mi < 4; mi++)
#pragma unroll
            for (int ni = 0; ni < 4; ni++) {
                const int r = bm + m0 + mi * 16 + gid;
                const int c = n0 + ni * 8 + 2 * tig;
                *(float2*)&g_u[(size_t)r * LH + bn + c]       = make_float2(acc[mi][ni][0], acc[mi][ni][1]);
                *(float2*)&g_u[(size_t)(r + 8) * LH + bn + c] = make_float2(acc[mi][ni][2], acc[mi][ni][3]);
            }
    } else {
        // V/Q/K -> fp16 staged through smem for coalesced 16B stores
        __half (*sout)[136] = reinterpret_cast<__half(*)[136]>(sh);
        // mainloop smem reads are fenced by the trailing __syncthreads() of it=7
#pragma unroll
        for (int mi = 0; mi < 4; mi++)
#pragma unroll
            for (int ni = 0; ni < 4; ni++) {
                const int r = m0 + mi * 16 + gid;
                const int c = n0 + ni * 8 + 2 * tig;
                *(__half2*)&sout[r][c]     = __floats2half2_rn(acc[mi][ni][0], acc[mi][ni][1]);
                *(__half2*)&sout[r + 8][c] = __floats2half2_rn(acc[mi][ni][2], acc[mi][ni][3]);
            }
        __syncthreads();
        const int qc0 = bn - 512;
#pragma unroll
        for (int i = 0; i < 8; i++) {
            const int idx = t + i * 256;          // 0..2047
            const int row = idx >> 4, ch = idx & 15;
            *(float4*)&g_qkv[(size_t)(bm + row) * QKV_W + qc0 + ch * 8] =
                *(float4*)&sout[row][ch * 8];
        }
    }
}

// ---------------- 3) causal silu-attention: f16-accum S GEMM, register P ----------------
// grid (32 bh, 16 q-tiles), 128 threads = 4 warps; warp owns 32 q-rows x 64-key tiles (32-key subtiles).
// smem (halves): 4-stage KV ring, stage s @ s*9216: K [64][72] @0, V @4608.
// Q staged in stage 3 (dead after fragment extraction at pair 0, then reused by the ring).
#define ATTN_SMEM (4 * 9216 * 2)   // 73728 B
__global__ __launch_bounds__(128, 3) void attn_kernel() {
    extern __shared__ __half sh[];

    const int t = threadIdx.x;
    const int wid = t >> 5, lane = t & 31;
    const int gid = lane >> 2, tig = lane & 3;

    const int nt = 15 - blockIdx.y;     // largest workloads in wave 1
    const int bh = blockIdx.x;
    const int b = bh >> 3, h = bh & 7;
    const int nbase = nt << 7;
    const size_t base = (size_t)b * SS;
    const int hd = h << 6;

    const int qrow = wid * 32;                  // warp's local Q-row base (32 rows)
    const int rowmin = nbase + qrow;            // warp's min global q-row

    const int lrow = t >> 3, lq = t & 7;        // loaders (128 threads)

#define LOAD_KV_ST(st, m0b) do {                                                        \
        __half* sk = sh + (st) * 9216;                                                  \
        __half* sv = sk + 4608;                                                         \
        _Pragma("unroll")                                                               \
        for (int i = 0; i < 4; i++) {                                                   \
            const int row = lrow + i * 16;                                              \
            const __half* rowp = &g_qkv[(base + (m0b) + row) * QKV_W + hd + lq * 8];    \
            cpa16(sk + row * 72 + lq * 8, rowp + QO_K);                                 \
            cpa16(sv + row * 72 + lq * 8, rowp + QO_V);                                 \
        }                                                                               \
    } while (0)

    const int nkt = 2 * nt + 2;                 // always even, >= 2

    // Preload: Q -> stage 3 region, then KV tiles 0,1,2 (clamped)
    {
        __half* qd = sh + 3 * 9216;
#pragma unroll
        for (int i = 0; i < 8; i++) {
            const int row = lrow + i * 16;
            cpa16(qd + row * 72 + lq * 8,
                  &g_qkv[(base + nbase + row) * QKV_W + QO_Q + hd + lq * 8]);
        }
    }
    LOAD_KV_ST(0, 0); cp_commit();
    LOAD_KV_ST(1, 64); cp_commit();
    { const int t2i = (2 < nkt) ? 2 : nkt - 1; LOAD_KV_ST(2, t2i << 6); cp_commit(); }

    uint32_t aq[2][4][4];       // Q fragments, loop-resident
    float o[2][8][4] = {};

    const int npair = nkt >> 1;
    for (int p = 0; p < npair; ++p) {
        cp_wait0();
        __syncthreads();
        if (p == 0) {
            const uint32_t qBase = smem_u32(sh + 3 * 9216);
#pragma unroll
            for (int g = 0; g < 2; g++)
#pragma unroll
                for (int ks = 0; ks < 4; ks++)
                    ldsm_x4(aq[g][ks], qBase +
                            (uint32_t)((qrow + g * 16 + (lane & 15)) * 144
                                       + (ks * 16 + ((lane >> 4) << 3)) * 2));
            __syncthreads();    // fence Q reads before stage-3 prefetch below
        }
        // prefetch tiles 2p+2, 2p+3 into stages consumed last pair (safe post-sync)
        if (2 * p + 2 < nkt) { LOAD_KV_ST((2 * p + 2) & 3, (2 * p + 2) << 6); cp_commit(); }
        if (2 * p + 3 < nkt) { LOAD_KV_ST((2 * p + 3) & 3, (2 * p + 3) << 6); cp_commit(); }

        // process kt = 2p, 2p+1 back-to-back, no intervening sync
#pragma unroll
        for (int hf = 0; hf < 2; hf++) {
            const int kt = 2 * p + hf;
            const uint32_t kBase = smem_u32(sh + (kt & 3) * 9216);
            const uint32_t vBase = kBase + 9216;    // +4608 halves
            const int m0b = kt << 6;

#pragma unroll
            for (int sub = 0; sub < 2; sub++) {
                const int s32 = m0b + sub * 32;
                if (s32 > rowmin + 31) continue;        // subtile fully masked (warp-uniform)

                // ---- S = Q(32x64) @ K^T(64x32), f16 accumulation ----
                uint32_t s2[2][4][2] = {};              // packed half2 accumulators
#pragma unroll
                for (int ks = 0; ks < 4; ks++) {
                    const int d0h = ks * 16;
                    uint32_t bk[2][4];
#pragma unroll
                    for (int pp = 0; pp < 2; pp++) {
                        const int row = sub * 32 + pp * 16 + (lane & 7) + ((lane >> 4) << 3);
                        const int kadd = ((lane >> 3) & 1) << 3;
                        ldsm_x4(bk[pp], kBase + (uint32_t)(row * 144 + (d0h + kadd) * 2));
                    }
#pragma unroll
                    for (int g = 0; g < 2; g++)
#pragma unroll
                        for (int nb = 0; nb < 4; nb++)
                            mma_f16acc(s2[g][nb], aq[g][ks], &bk[nb >> 1][(nb & 1) * 2]);
                }

                // ---- causal mask (partial subtiles only; exact-int fp16 compare) ----
                if (s32 + 31 > rowmin) {
#pragma unroll
                    for (int g = 0; g < 2; g++) {
                        const float rbase = (float)(rowmin + g * 16 + gid);
#pragma unroll
                        for (int nb = 0; nb < 4; nb++) {
                            const int mm = s32 + nb * 8 + 2 * tig;
                            const __half2 cols = __floats2half2_rn((float)mm, (float)(mm + 1));
#pragma unroll
                            for (int rg = 0; rg < 2; rg++) {
                                const __half2 rows = __half2half2(__float2half(rbase + rg * 8));
                                const __half2 keep = __hle2(cols, rows);   // col<=row -> 1.0
                                s2[g][nb][rg] = h2u(__hmul2(u2h(s2[g][nb][rg]), keep));
                            }
                        }
                    }
                }

                // ---- silu (f16x2) directly on accumulator regs = A-fragments ----
                uint32_t pf[2][2][4];
#pragma unroll
                for (int g = 0; g < 2; g++)
#pragma unroll
                    for (int kb = 0; kb < 2; kb++) {
                        pf[g][kb][0] = silu2(s2[g][2 * kb][0]);
                        pf[g][kb][1] = silu2(s2[g][2 * kb][1]);
                        pf[g][kb][2] = silu2(s2[g][2 * kb + 1][0]);
                        pf[g][kb][3] = silu2(s2[g][2 * kb + 1][1]);
                    }

                // ---- O += P(32x32) @ V(32x64), fp32 accumulation ----
#pragma unroll
                for (int kb = 0; kb < 2; kb++) {
                    const int mk = sub * 32 + kb * 16;
                    uint32_t bv[4][4];
#pragma unroll
                    for (int db = 0; db < 4; db++) {
                        const int row = mk + (lane & 7) + (((lane >> 3) & 1) << 3);
                        const int col = db * 16 + ((lane >> 4) << 3);
                        ldsm_x4_t(bv[db], vBase + (uint32_t)(row * 144 + col * 2));
                    }
#pragma unroll
                    for (int g = 0; g < 2; g++)
#pragma unroll
                        for (int dnb = 0; dnb < 8; dnb++)
                            mma_f16(o[g][dnb], pf[g][kb], &bv[dnb >> 1][(dnb & 1) * 2]);
                }
            }
        }
    }

    // ---- write O ----
#pragma unroll
    for (int g = 0; g < 2; g++)
#pragma unroll
        for (int dnb = 0; dnb < 8; dnb++) {
            const size_t r = base + rowmin + g * 16 + gid;
            const int c = hd + dnb * 8 + 2 * tig;
            *(float2*)&g_attn[r * LH + c]       = make_float2(o[g][dnb][0], o[g][dnb][1]);
            *(float2*)&g_attn[(r + 8) * LH + c] = make_float2(o[g][dnb][2], o[g][dnb][3]);
        }
}

// ---------------- 4) output LN * u + residual (float4) ----------------
__global__ __launch_bounds__(128) void out_kernel(const float* __restrict__ ue,
                                                  const float* __restrict__ g,
                                                  const float* __restrict__ be,
                                                  float* __restrict__ out) {
    const int row = blockIdx.x, t = threadIdx.x;
    const float4 a = *(const float4*)&g_attn[(size_t)row * LH + 4 * t];
    float2 r = block_reduce_sum2_128(a.x + a.y + a.z + a.w,
                                     a.x * a.x + a.y * a.y + a.z * a.z + a.w * a.w);
    float mu = r.x * (1.f / 512.f);
    float var = r.y * (1.f / 512.f) - mu * mu;
    float rs = rsqrtf(var + 1e-6f);
    const float4 gg = *(const float4*)&g[4 * t];
    const float4 bb = *(const float4*)&be[4 * t];
    const float4 uu = *(const float4*)&g_u[(size_t)row * LH + 4 * t];
    const float4 ee = *(const float4*)&ue[(size_t)row * EE + 4 * t];
    float4 yy;
    yy.x = ee.x + ((a.x - mu) * rs * gg.x + bb.x) * uu.x;
    yy.y = ee.y + ((a.y - mu) * rs * gg.y + bb.y) * uu.y;
    yy.z = ee.z + ((a.z - mu) * rs * gg.z + bb.z) * uu.z;
    yy.w = ee.w + ((a.w - mu) * rs * gg.w + bb.w) * uu.w;
    *(float4*)&out[(size_t)row * EE + 4 * t] = yy;
}

extern "C" void kernel_launch(void* const* d_in, const int* in_sizes, int n_in,
                              void* d_out, int out_size) {
    (void)in_sizes; (void)n_in; (void)out_size;
    const float* ue   = (const float*)d_in[0];
    const float* uvqk = (const float*)d_in[2];
    const float* ing  = (const float*)d_in[3];
    const float* inb  = (const float*)d_in[4];
    const float* outg = (const float*)d_in[5];
    const float* outb = (const float*)d_in[6];
    float* out = (float*)d_out;

    cudaFuncSetAttribute(gemm_proj_kernel, cudaFuncAttributeMaxDynamicSharedMemorySize, PROJ_SMEM);
    cudaFuncSetAttribute(attn_kernel, cudaFuncAttributeMaxDynamicSharedMemorySize, ATTN_SMEM);

    ln_in_kernel<<<NROW, 128>>>(ue, ing, inb);
    transpose_w_kernel<<<dim3(FF / 32, EE / 32), dim3(32, 8)>>>(uvqk);
    gemm_proj_kernel<<<dim3(FF / 128, NROW / 128), 256, PROJ_SMEM>>>();
    attn_kernel<<<dim3(BB * HH, SS / 128), 128, ATTN_SMEM>>>();
    out_kernel<<<NROW, 128>>>(ue, outg, outb, out);
}